// round 10
// baseline (speedup 1.0000x reference)
#include <cuda_runtime.h>
#include <cuda_fp16.h>
#include <math.h>
#include <stdint.h>
#include <stddef.h>

#define BATCH 16
#define NTOK  3136
#define CH    768
#define NH    16
#define HD    48
#define KDIM  768
#define MROWS (BATCH*NTOK)   // 50176
#define BH    (BATCH*NH)     // 256
#define SPLIT 7
#define TOKSP (NTOK/SPLIT)   // 448

// ----------------------------- device scratch ------------------------------
__device__ __half g_xh  [(size_t)MROWS * KDIM];
__device__ __half g_qT  [(size_t)BH * HD * NTOK];   // [bh][d][n] fp16
__device__ __half g_kT  [(size_t)BH * HD * NTOK];
__device__ __half g_v   [(size_t)MROWS * CH];       // [token][h*48+d] fp16
__device__ __half g_ah  [(size_t)MROWS * CH];
__device__ __half g_wq  [(size_t)(3 * CH) * KDIM];
__device__ __half g_wp  [(size_t)CH * KDIM];
__device__ float  g_gram[(size_t)BH * SPLIT * HD * HD];
__device__ float  g_ssq [(size_t)BH * SPLIT * HD];
__device__ float  g_ssk [(size_t)BH * SPLIT * HD];
__device__ __half g_attnh[(size_t)BH * HD * HD];

// ----------------------------- PTX helpers ---------------------------------
__device__ __forceinline__ uint32_t smem_u32(const void* p) {
    return (uint32_t)__cvta_generic_to_shared(p);
}

__device__ __forceinline__ void mma16816(float* c, const uint32_t* a, const uint32_t* b) {
    asm volatile(
        "mma.sync.aligned.m16n8k16.row.col.f32.f16.f16.f32 "
        "{%0,%1,%2,%3}, {%4,%5,%6,%7}, {%8,%9}, {%0,%1,%2,%3};"
        : "+f"(c[0]), "+f"(c[1]), "+f"(c[2]), "+f"(c[3])
        : "r"(a[0]), "r"(a[1]), "r"(a[2]), "r"(a[3]), "r"(b[0]), "r"(b[1]));
}

__device__ __forceinline__ void ldsm4(uint32_t* r, uint32_t addr) {
    asm volatile("ldmatrix.sync.aligned.m8n8.x4.shared.b16 {%0,%1,%2,%3}, [%4];"
        : "=r"(r[0]), "=r"(r[1]), "=r"(r[2]), "=r"(r[3]) : "r"(addr));
}

#define CP16(dst, src) \
    asm volatile("cp.async.cg.shared.global [%0], [%1], 16;" :: "r"(dst), "l"(src))
#define CP_COMMIT()  asm volatile("cp.async.commit_group;" ::: "memory")
#define CP_WAIT0()   asm volatile("cp.async.wait_group 0;" ::: "memory")
#define CP_WAIT1()   asm volatile("cp.async.wait_group 1;" ::: "memory")
#define CP_WAIT2()   asm volatile("cp.async.wait_group 2;" ::: "memory")

// ---------------------------------------------------------------------------
// fp32 -> fp16 convert
// ---------------------------------------------------------------------------
__global__ void conv_kernel(const float4* __restrict__ in,
                            __half2* __restrict__ out, int n4)
{
    int i = blockIdx.x * blockDim.x + threadIdx.x;
    if (i >= n4) return;
    float4 v = in[i];
    out[2 * i + 0] = __floats2half2_rn(v.x, v.y);
    out[2 * i + 1] = __floats2half2_rn(v.z, v.w);
}

// ---------------------------------------------------------------------------
// Transpose + convert: W[K,N] fp32 -> Wt [N,K] fp16
// ---------------------------------------------------------------------------
__global__ void tconv_kernel(const float* __restrict__ W,
                             __half* __restrict__ T, int K, int N)
{
    __shared__ float tile[32][33];
    int n0 = blockIdx.x * 32, k0 = blockIdx.y * 32;
    int tx = threadIdx.x, ty = threadIdx.y;   // 32 x 8
#pragma unroll
    for (int j = 0; j < 32; j += 8)
        tile[ty + j][tx] = W[(size_t)(k0 + ty + j) * N + n0 + tx];
    __syncthreads();
#pragma unroll
    for (int j = 0; j < 32; j += 8)
        T[(size_t)(n0 + ty + j) * K + k0 + tx] = __float2half_rn(tile[tx][ty + j]);
}

// ---------------------------------------------------------------------------
// GEMM geometry: CTA tile 256(M) x 128(N), K-chunk 64, 4 stages, 1 barrier/it.
// 8 warps @ 64x64. Rows 144B (9x16B, conflict-free). 1 CTA/SM.
// ---------------------------------------------------------------------------
#define ROWB     144
#define A_B      (256 * ROWB)                // 36864
#define STAGE_B  (384 * ROWB)                // 55296 (A 256 rows + B 128 rows)
#define NSTAGE   4
#define SMEM_GEMM (NSTAGE * STAGE_B)         // 221184
#define KC       64
#define NITER    (KDIM / KC)                 // 12

#define GEMM_PRELUDE(Aptr, Bptr)                                               \
    extern __shared__ char sm[];                                               \
    const int tid  = threadIdx.x;                                              \
    const int wid  = tid >> 5;                                                 \
    const int lane = tid & 31;                                                 \
    const size_t m0 = (size_t)blockIdx.y * 256;                                \
    const size_t n0 = (size_t)blockIdx.x * 128;                                \
    const int lr0  = tid >> 3;            /* 0..31 */                          \
    const int lseg = tid & 7;                                                  \
    const uint32_t sbase = smem_u32(sm);                                       \
    const uint32_t dA = sbase + lr0 * ROWB + lseg * 16;                        \
    const uint32_t dB = sbase + A_B + lr0 * ROWB + lseg * 16;                  \
    const __half* sA = (Aptr) + (m0 + lr0) * KDIM + lseg * 8;                  \
    const __half* sB = (Bptr) + (n0 + lr0) * KDIM + lseg * 8;                  \
    auto load_stage = [&](int kc, int s) {                                     \
        _Pragma("unroll")                                                      \
        for (int i = 0; i < 8; i++)                                            \
            CP16(dA + s * STAGE_B + i * 32 * ROWB, sA + kc + (size_t)i * 32 * KDIM); \
        _Pragma("unroll")                                                      \
        for (int i = 0; i < 4; i++)                                            \
            CP16(dB + s * STAGE_B + i * 32 * ROWB, sB + kc + (size_t)i * 32 * KDIM); \
    };                                                                         \
    const int warp_m = wid & 3;                                                \
    const int warp_n = wid >> 2;                                               \
    const int gq  = lane >> 3;                                                 \
    const int r8 = lane & 7;                                                   \
    const uint32_t a_off = (uint32_t)((warp_m * 64 + (gq & 1) * 8 + r8) * ROWB + (gq >> 1) * 16); \
    const uint32_t b_off = (uint32_t)((warp_n * 64 + ((gq >> 1) & 1) * 8 + r8) * ROWB + (gq & 1) * 16); \
    float acc[4][8][4];                                                        \
    _Pragma("unroll")                                                          \
    for (int i = 0; i < 4; i++)                                                \
        _Pragma("unroll")                                                      \
        for (int j = 0; j < 8; j++)                                            \
            _Pragma("unroll")                                                  \
            for (int q = 0; q < 4; q++) acc[i][j][q] = 0.f;                    \
    load_stage(0, 0);      CP_COMMIT();                                        \
    load_stage(KC, 1);     CP_COMMIT();                                        \
    load_stage(2 * KC, 2); CP_COMMIT();                                        \
    for (int it = 0; it < NITER; it++) {                                       \
        CP_WAIT2();                                                            \
        __syncthreads();                                                       \
        if (it + 3 < NITER) load_stage((it + 3) * KC, (it + 3) % NSTAGE);      \
        CP_COMMIT();                                                           \
        const uint32_t st = sbase + (it % NSTAGE) * STAGE_B;                   \
        uint32_t af[2][4][4];                                                  \
        _Pragma("unroll")                                                      \
        for (int mt = 0; mt < 4; mt++)                                         \
            ldsm4(af[0][mt], st + a_off + mt * 16 * ROWB);                     \
        _Pragma("unroll")                                                      \
        for (int kk = 0; kk < 4; kk++) {                                       \
            const uint32_t kb = kk * 32;                                       \
            const int cur = kk & 1;                                            \
            uint32_t bf[8][2], t4[4];                                          \
            _Pragma("unroll")                                                  \
            for (int j = 0; j < 4; j++) {                                      \
                ldsm4(t4, st + A_B + b_off + j * 16 * ROWB + kb);              \
                bf[2 * j + 0][0] = t4[0]; bf[2 * j + 0][1] = t4[1];            \
                bf[2 * j + 1][0] = t4[2]; bf[2 * j + 1][1] = t4[3];            \
            }                                                                  \
            if (kk < 3) {                                                      \
                _Pragma("unroll")                                              \
                for (int mt = 0; mt < 4; mt++)                                 \
                    ldsm4(af[cur ^ 1][mt], st + a_off + mt * 16 * ROWB + kb + 32); \
            }                                                                  \
            _Pragma("unroll")                                                  \
            for (int mt = 0; mt < 4; mt++)                                     \
                _Pragma("unroll")                                              \
                for (int nt = 0; nt < 8; nt++)                                 \
                    mma16816(acc[mt][nt], af[cur][mt], bf[nt]);                \
        }                                                                      \
    }

// ---------------------------------------------------------------------------
// GEMM1: qkv = x @ qkv_w^T, fp16 outputs in XCA layouts.
// ---------------------------------------------------------------------------
__global__ __launch_bounds__(256, 1) void gemm_qkv(
    const __half* __restrict__ A, const __half* __restrict__ B,
    __half* __restrict__ Qt, __half* __restrict__ Kt, __half* __restrict__ Vp)
{
    GEMM_PRELUDE(A, B)

    // ---- epilogue ----
    CP_WAIT0();
    __syncthreads();   // all smem reads done; safe to reuse sm
    const int section = (int)(n0 / 768);   // 0:q 1:k 2:v
    const int crow = warp_m * 64 + (lane >> 2);
    const int ccol = warp_n * 64 + (lane & 3) * 2;

    if (section == 2) {
#pragma unroll
        for (int mt = 0; mt < 4; mt++) {
#pragma unroll
            for (int nt = 0; nt < 8; nt++) {
                size_t row = m0 + crow + mt * 16;
                int vc = (int)(n0 - 1536) + ccol + nt * 8;
                __half2 h0 = __floats2half2_rn(acc[mt][nt][0], acc[mt][nt][1]);
                __half2 h1 = __floats2half2_rn(acc[mt][nt][2], acc[mt][nt][3]);
                *(__half2*)(Vp + row * CH + vc) = h0;
                *(__half2*)(Vp + (row + 8) * CH + vc) = h1;
            }
        }
    } else {
        // transpose through smem: [col 128][token 256], row stride 528B
#pragma unroll
        for (int mt = 0; mt < 4; mt++) {
#pragma unroll
            for (int nt = 0; nt < 8; nt++) {
                int col = ccol + nt * 8;
                int row = crow + mt * 16;
                *(__half*)(sm + (size_t)col * 528 + row * 2)             = __float2half_rn(acc[mt][nt][0]);
                *(__half*)(sm + (size_t)(col + 1) * 528 + row * 2)       = __float2half_rn(acc[mt][nt][1]);
                *(__half*)(sm + (size_t)col * 528 + (row + 8) * 2)       = __float2half_rn(acc[mt][nt][2]);
                *(__half*)(sm + (size_t)(col + 1) * 528 + (row + 8) * 2) = __float2half_rn(acc[mt][nt][3]);
            }
        }
        __syncthreads();
        __half* dst = (section == 0) ? Qt : Kt;
        const int base_gc = (int)n0 - section * 768;
#pragma unroll
        for (int i = 0; i < 16; i++) {
            int idx = tid + i * 256;          // 0..4095
            int col = idx >> 5, tv = idx & 31;
            uint4 val = *(uint4*)(sm + (size_t)col * 528 + tv * 16);
            int gc = base_gc + col;
            int hh = gc / 48, dd = gc - hh * 48;
            size_t tok = m0 + tv * 8;
            int b = (int)(tok / NTOK);
            int n = (int)(tok - (size_t)b * NTOK);
            *(uint4*)(dst + ((size_t)(b * 16 + hh) * HD + dd) * NTOK + n) = val;
        }
    }
}

// ---------------------------------------------------------------------------
// GEMM2: out = att @ proj_w^T + bias, fp32 out.
// ---------------------------------------------------------------------------
__global__ __launch_bounds__(256, 1) void gemm_mma(
    const __half* __restrict__ A, const __half* __restrict__ B,
    float* __restrict__ C, int N, const float* __restrict__ bias)
{
    GEMM_PRELUDE(A, B)

    const int crow = warp_m * 64 + (lane >> 2);
    const int ccol = warp_n * 64 + (lane & 3) * 2;
#pragma unroll
    for (int mt = 0; mt < 4; mt++) {
#pragma unroll
        for (int nt = 0; nt < 8; nt++) {
            float b0 = __ldg(bias + n0 + ccol + nt * 8);
            float b1 = __ldg(bias + n0 + ccol + nt * 8 + 1);
            float2 v0 = {acc[mt][nt][0] + b0, acc[mt][nt][1] + b1};
            float2 v1 = {acc[mt][nt][2] + b0, acc[mt][nt][3] + b1};
            float* p0 = C + (m0 + crow + mt * 16) * (size_t)N + n0 + ccol + nt * 8;
            float* p1 = p0 + 8 * (size_t)N;
            *(float2*)p0 = v0;
            *(float2*)p1 = v1;
        }
    }
}

// ---------------------------------------------------------------------------
// Gram via mma (unchanged from R8/R9).
// ---------------------------------------------------------------------------
#define GROWB  144
#define GTILE  (48 * GROWB)
#define GSTAGE (2 * GTILE)
#define GRED   (2 * GSTAGE)
#define SMEM_GRAM (GRED + 4 * HD * HD * 4)

__global__ __launch_bounds__(256) void gram_kernel()
{
    extern __shared__ char sm[];
    const int tid  = threadIdx.x;
    const int wid  = tid >> 5;
    const int lane = tid & 31;
    const int bh = blockIdx.x;
    const int sp = blockIdx.y;
    const uint32_t sbase = smem_u32(sm);

    const __half* qbase = g_qT + (size_t)bh * HD * NTOK + sp * TOKSP;
    const __half* kbase = g_kT + (size_t)bh * HD * NTOK + sp * TOKSP;

    uint32_t ldst[3];
    const __half* lsrc[3];
#pragma unroll
    for (int i = 0; i < 3; i++) {
        int c = tid + i * 256;
        int cc = (c < 384) ? c : c - 384;
        int r = cc >> 3, seg = cc & 7;
        ldst[i] = sbase + ((c < 384) ? 0 : GTILE) + r * GROWB + seg * 16;
        lsrc[i] = ((c < 384) ? qbase : kbase) + (size_t)r * NTOK + seg * 8;
    }
    auto load_stage = [&](int kc, int s) {
#pragma unroll
        for (int i = 0; i < 3; i++)
            CP16(ldst[i] + s * GSTAGE, lsrc[i] + kc);
    };

    const int g  = lane >> 3;
    const int r8 = lane & 7;
    const uint32_t a_off = (uint32_t)(((g & 1) * 8 + r8) * GROWB + (g >> 1) * 16);
    const uint32_t b_off = (uint32_t)((((g >> 1) & 1) * 8 + r8) * GROWB + (g & 1) * 16);

    float acc[3][6][4];
#pragma unroll
    for (int i = 0; i < 3; i++)
#pragma unroll
        for (int j = 0; j < 6; j++)
#pragma unroll
            for (int q = 0; q < 4; q++) acc[i][j][q] = 0.f;

    const int t2 = ((wid - 4) & 1) * 32 + lane;
    const bool isq = (wid == 4 || wid == 5);
    float nsum = 0.f;

    load_stage(0, 0);
    CP_COMMIT();

    for (int c = 0; c < SPLIT; c++) {
        if (c + 1 < SPLIT) {
            load_stage((c + 1) * 64, (c + 1) & 1);
            CP_COMMIT();
            CP_WAIT1();
        } else {
            CP_WAIT0();
        }
        __syncthreads();
        const uint32_t st = sbase + (c & 1) * GSTAGE;
        if (wid < 4) {
            const uint32_t kb = wid * 32;
            uint32_t af[3][4], bf[6][2];
#pragma unroll
            for (int mt = 0; mt < 3; mt++)
                ldsm4(af[mt], st + a_off + mt * 16 * GROWB + kb);
#pragma unroll
            for (int j = 0; j < 3; j++) {
                uint32_t t4[4];
                ldsm4(t4, st + GTILE + b_off + j * 16 * GROWB + kb);
                bf[j * 2 + 0][0] = t4[0]; bf[j * 2 + 0][1] = t4[1];
                bf[j * 2 + 1][0] = t4[2]; bf[j * 2 + 1][1] = t4[3];
            }
#pragma unroll
            for (int mt = 0; mt < 3; mt++)
#pragma unroll
                for (int nt = 0; nt < 6; nt++)
                    mma16816(acc[mt][nt], af[mt], bf[nt]);
        } else if (t2 < 48) {
            const uint32_t rowaddr = st + (isq ? 0 : GTILE) + t2 * GROWB;
#pragma unroll
            for (int i = 0; i < 32; i++) {
                uint32_t u;
                asm volatile("ld.shared.b32 %0, [%1];" : "=r"(u) : "r"(rowaddr + i * 4));
                float2 f = __half22float2(*(__half2*)&u);
                nsum = fmaf(f.x, f.x, nsum);
                nsum = fmaf(f.y, f.y, nsum);
            }
        }
        __syncthreads();
    }

    if (wid >= 4 && t2 < 48) {
        float* dst = isq ? g_ssq : g_ssk;
        dst[((size_t)bh * SPLIT + sp) * HD + t2] = nsum;
    }

    float* red = (float*)(sm + GRED);
    if (wid < 4) {
        float* rw = red + wid * (HD * HD);
#pragma unroll
        for (int mt = 0; mt < 3; mt++)
#pragma unroll
            for (int nt = 0; nt < 6; nt++) {
                int row = mt * 16 + (lane >> 2);
                int col = nt * 8 + (lane & 3) * 2;
                *(float2*)(rw + row * HD + col) = *(float2*)&acc[mt][nt][0];
                *(float2*)(rw + (row + 8) * HD + col) = *(float2*)&acc[mt][nt][2];
            }
    }
    __syncthreads();
    float* gout = g_gram + ((size_t)bh * SPLIT + sp) * (HD * HD);
#pragma unroll
    for (int i = 0; i < 9; i++) {
        int el = tid + i * 256;
        gout[el] = red[el] + red[HD * HD + el] + red[2 * HD * HD + el] + red[3 * HD * HD + el];
    }
}

// ---------------------------------------------------------------------------
// Softmax (unchanged).
// ---------------------------------------------------------------------------
__global__ __launch_bounds__(256) void softmax_kernel(const float* __restrict__ temperature)
{
    __shared__ float attn[48][52];
    __shared__ float invq[48];
    __shared__ float invk[48];

    const int bh = blockIdx.x;
    const int h = bh & 15;
    const int tid = threadIdx.x;
    const int r = tid >> 4;
    const int c = tid & 15;

    if (tid < 48) {
        float s = 0.f;
#pragma unroll
        for (int p = 0; p < SPLIT; p++)
            s += g_ssq[((size_t)bh * SPLIT + p) * HD + tid];
        invq[tid] = 1.f / fmaxf(sqrtf(s), 1e-12f);
    } else if (tid < 96) {
        float s = 0.f;
#pragma unroll
        for (int p = 0; p < SPLIT; p++)
            s += g_ssk[((size_t)bh * SPLIT + p) * HD + tid - 48];
        invk[tid - 48] = 1.f / fmaxf(sqrtf(s), 1e-12f);
    }

    const float* gin = g_gram + (size_t)bh * SPLIT * (HD * HD);
    float sums[3][3];
#pragma unroll
    for (int i = 0; i < 3; i++)
#pragma unroll
        for (int j = 0; j < 3; j++) {
            float s = 0.f;
            int idx = (3 * r + i) * HD + 3 * c + j;
#pragma unroll
            for (int p = 0; p < SPLIT; p++)
                s += gin[p * (HD * HD) + idx];
            sums[i][j] = s;
        }
    __syncthreads();

    const float temp = temperature[h];
#pragma unroll
    for (int i = 0; i < 3; i++)
#pragma unroll
        for (int j = 0; j < 3; j++)
            attn[3 * r + i][3 * c + j] =
                sums[i][j] * invq[3 * r + i] * invk[3 * c + j] * temp;
    __syncthreads();

    const int lane = tid & 31;
    const int w = tid >> 5;
    for (int d = w; d < 48; d += 8) {
        float x1 = attn[d][lane];
        float x2 = (lane < 16) ? attn[d][32 + lane] : -1e30f;
        float m = fmaxf(x1, x2);
#pragma unroll
        for (int o = 16; o > 0; o >>= 1)
            m = fmaxf(m, __shfl_xor_sync(0xffffffffu, m, o));
        float p1 = expf(x1 - m);
        float p2 = (lane < 16) ? expf(x2 - m) : 0.f;
        float s = p1 + p2;
#pragma unroll
        for (int o = 16; o > 0; o >>= 1)
            s += __shfl_xor_sync(0xffffffffu, s, o);
        float inv = 1.f / s;
        __half* arow = g_attnh + (size_t)bh * (HD * HD) + d * HD;
        arow[lane] = __float2half_rn(p1 * inv);
        if (lane < 16) arow[32 + lane] = __float2half_rn(p2 * inv);
    }
}

// ---------------------------------------------------------------------------
// AV via mma (unchanged).
// ---------------------------------------------------------------------------
#define VROWB  112
#define ATN_B  (48 * VROWB)
#define VSTG   (128 * VROWB)
#define SMEM_AV (ATN_B + 2 * VSTG)

__global__ __launch_bounds__(256) void av_kernel()
{
    extern __shared__ char sm[];
    const int tid  = threadIdx.x;
    const int wid  = tid >> 5;
    const int lane = tid & 31;
    const int bh = blockIdx.x;
    const int sp = blockIdx.y;
    const int b = bh >> 4;
    const int h = bh & 15;
    const uint32_t sbase = smem_u32(sm);
    const uint32_t vs0 = sbase + ATN_B;

    const size_t tokflat = (size_t)b * NTOK + sp * TOKSP;

    for (int idx = tid; idx < 288; idx += 256) {
        int row = idx / 6, seg = idx % 6;
        uint4 val = *(const uint4*)(g_attnh + (size_t)bh * (HD * HD) + row * HD + seg * 8);
        *(uint4*)(sm + row * VROWB + seg * 16) = val;
    }

    int lrow[3], lseg[3];
#pragma unroll
    for (int i = 0; i < 3; i++) {
        int cc = tid + i * 256;
        lrow[i] = cc / 6;
        lseg[i] = cc % 6;
    }
    auto load_stage = [&](int t0, int rows, int s) {
#pragma unroll
        for (int i = 0; i < 3; i++) {
            if (lrow[i] < rows) {
                const __half* src = g_v + (tokflat + t0 + lrow[i]) * CH + h * HD + lseg[i] * 8;
                CP16(vs0 + s * VSTG + lrow[i] * VROWB + lseg[i] * 16, src);
            }
        }
    };

    const int g  = lane >> 3;
    const int r8 = lane & 7;
    const uint32_t a_off = (uint32_t)(((g & 1) * 8 + r8) * VROWB + (g >> 1) * 16);
    const uint32_t b_off = (uint32_t)((((g >> 1) & 1) * 8 + r8) * VROWB + (g & 1) * 16);

    load_stage(0, 128, 0);
    CP_COMMIT();
    __syncthreads();

    uint32_t bf[3][6][2];
#pragma unroll
    for (int k16 = 0; k16 < 3; k16++) {
#pragma unroll
        for (int j = 0; j < 3; j++) {
            uint32_t t4[4];
            ldsm4(t4, sbase + b_off + j * 16 * VROWB + k16 * 32);
            bf[k16][j * 2 + 0][0] = t4[0]; bf[k16][j * 2 + 0][1] = t4[1];
            bf[k16][j * 2 + 1][0] = t4[2]; bf[k16][j * 2 + 1][1] = t4[3];
        }
    }

    const int NIT = (TOKSP + 127) / 128;
    for (int it = 0; it < NIT; it++) {
        const int rows_this = min(128, TOKSP - it * 128);
        if (it + 1 < NIT) {
            load_stage((it + 1) * 128, min(128, TOKSP - (it + 1) * 128), (it + 1) & 1);
            CP_COMMIT();
            CP_WAIT1();
        } else {
            CP_WAIT0();
        }
        __syncthreads();

        if (wid * 16 < rows_this) {
            const uint32_t st = vs0 + (it & 1) * VSTG + wid * 16 * VROWB;
            float acc[6][4];
#pragma unroll
            for (int j = 0; j < 6; j++)
#pragma unroll
                for (int q = 0; q < 4; q++) acc[j][q] = 0.f;
#pragma unroll
            for (int k16 = 0; k16 < 3; k16++) {
                uint32_t af[4];
                ldsm4(af, st + a_off + k16 * 32);
#pragma unroll
                for (int j = 0; j < 6; j++)
                    mma16816(acc[j], af, bf[k16][j]);
            }
            const size_t trow = tokflat + it * 128 + wid * 16 + (lane >> 2);
#pragma unroll
            for (int j = 0; j < 6; j++) {
                int d = j * 8 + (lane & 3) * 2;
                __half2 h0 = __floats2half2_rn(acc[j][0], acc[j][1]);
                __half2 h1 = __floats2half2_rn(acc[j][2], acc[j][3]);
                *(__half2*)(g_ah + trow * CH + h * HD + d) = h0;
                *(__half2*)(g_ah + (trow + 8) * CH + h * HD + d) = h1;
            }
        }
        __syncthreads();
    }
}

// ---------------------------------------------------------------------------
// Launch sequence
// ---------------------------------------------------------------------------
extern "C" void kernel_launch(void* const* d_in, const int* in_sizes, int n_in,
                              void* d_out, int out_size)
{
    const float* x           = (const float*)d_in[0];
    const float* qkv_w       = (const float*)d_in[1];
    const float* temperature = (const float*)d_in[2];
    const float* proj_w      = (const float*)d_in[3];
    const float* proj_b      = (const float*)d_in[4];
    float* out = (float*)d_out;

    __half *xh, *ah, *wq, *wp, *qT, *kT, *vv;
    cudaGetSymbolAddress((void**)&xh, g_xh);
    cudaGetSymbolAddress((void**)&ah, g_ah);
    cudaGetSymbolAddress((void**)&wq, g_wq);
    cudaGetSymbolAddress((void**)&wp, g_wp);
    cudaGetSymbolAddress((void**)&qT, g_qT);
    cudaGetSymbolAddress((void**)&kT, g_kT);
    cudaGetSymbolAddress((void**)&vv, g_v);

    cudaFuncSetAttribute(gemm_qkv, cudaFuncAttributeMaxDynamicSharedMemorySize, SMEM_GEMM);
    cudaFuncSetAttribute(gemm_mma, cudaFuncAttributeMaxDynamicSharedMemorySize, SMEM_GEMM);
    cudaFuncSetAttribute(gram_kernel, cudaFuncAttributeMaxDynamicSharedMemorySize, SMEM_GRAM);
    cudaFuncSetAttribute(av_kernel, cudaFuncAttributeMaxDynamicSharedMemorySize, SMEM_AV);

    int n4 = MROWS * KDIM / 4;
    conv_kernel<<<(n4 + 255) / 256, 256>>>((const float4*)x, (__half2*)xh, n4);

    tconv_kernel<<<dim3((3 * CH) / 32, KDIM / 32), dim3(32, 8)>>>(
        qkv_w, wq, KDIM, 3 * CH);
    tconv_kernel<<<dim3(CH / 32, KDIM / 32), dim3(32, 8)>>>(
        proj_w, wp, KDIM, CH);

    gemm_qkv<<<dim3((3 * CH) / 128, MROWS / 256), 256, SMEM_GEMM>>>(
        xh, wq, qT, kT, vv);

    gram_kernel<<<dim3(BH, SPLIT), 256, SMEM_GRAM>>>();
    softmax_kernel<<<BH, 256>>>(temperature);
    av_kernel<<<dim3(BH, SPLIT), 256, SMEM_AV>>>();

    gemm_mma<<<dim3(CH / 128, MROWS / 256), 256, SMEM_GEMM>>>(
        ah, wp, out, CH, proj_b);
}

// round 11
// speedup vs baseline: 1.0792x; 1.0792x over previous
#include <cuda_runtime.h>
#include <cuda_fp16.h>
#include <math.h>
#include <stdint.h>
#include <stddef.h>

#define BATCH 16
#define NTOK  3136
#define CH    768
#define NH    16
#define HD    48
#define KDIM  768
#define MROWS (BATCH*NTOK)   // 50176
#define BH    (BATCH*NH)     // 256
#define SPLIT 7
#define TOKSP (NTOK/SPLIT)   // 448

// ----------------------------- device scratch ------------------------------
__device__ __half g_xh  [(size_t)MROWS * KDIM];
__device__ __half g_qT  [(size_t)BH * HD * NTOK];   // [bh][d][n] fp16
__device__ __half g_kT  [(size_t)BH * HD * NTOK];
__device__ __half g_v   [(size_t)MROWS * CH];       // [token][h*48+d] fp16
__device__ __half g_ah  [(size_t)MROWS * CH];
__device__ __half g_wq  [(size_t)(3 * CH) * KDIM];
__device__ __half g_wp  [(size_t)CH * KDIM];
__device__ float  g_gram[(size_t)BH * SPLIT * HD * HD];
__device__ float  g_ssq [(size_t)BH * SPLIT * HD];
__device__ float  g_ssk [(size_t)BH * SPLIT * HD];
__device__ __half g_attnh[(size_t)BH * HD * HD];

// ----------------------------- PTX helpers ---------------------------------
__device__ __forceinline__ uint32_t smem_u32(const void* p) {
    return (uint32_t)__cvta_generic_to_shared(p);
}

__device__ __forceinline__ void mma16816(float* c, const uint32_t* a, const uint32_t* b) {
    asm volatile(
        "mma.sync.aligned.m16n8k16.row.col.f32.f16.f16.f32 "
        "{%0,%1,%2,%3}, {%4,%5,%6,%7}, {%8,%9}, {%0,%1,%2,%3};"
        : "+f"(c[0]), "+f"(c[1]), "+f"(c[2]), "+f"(c[3])
        : "r"(a[0]), "r"(a[1]), "r"(a[2]), "r"(a[3]), "r"(b[0]), "r"(b[1]));
}

__device__ __forceinline__ void ldsm4(uint32_t* r, uint32_t addr) {
    asm volatile("ldmatrix.sync.aligned.m8n8.x4.shared.b16 {%0,%1,%2,%3}, [%4];"
        : "=r"(r[0]), "=r"(r[1]), "=r"(r[2]), "=r"(r[3]) : "r"(addr));
}

#define CP16(dst, src) \
    asm volatile("cp.async.cg.shared.global [%0], [%1], 16;" :: "r"(dst), "l"(src))
#define CP_COMMIT()  asm volatile("cp.async.commit_group;" ::: "memory")
#define CP_WAIT0()   asm volatile("cp.async.wait_group 0;" ::: "memory")
#define CP_WAIT1()   asm volatile("cp.async.wait_group 1;" ::: "memory")

// ---------------------------------------------------------------------------
// fp32 -> fp16 convert
// ---------------------------------------------------------------------------
__global__ void conv_kernel(const float4* __restrict__ in,
                            __half2* __restrict__ out, int n4)
{
    int i = blockIdx.x * blockDim.x + threadIdx.x;
    if (i >= n4) return;
    float4 v = in[i];
    out[2 * i + 0] = __floats2half2_rn(v.x, v.y);
    out[2 * i + 1] = __floats2half2_rn(v.z, v.w);
}

// ---------------------------------------------------------------------------
// Transpose + convert: W[K,N] fp32 -> Wt [N,K] fp16
// ---------------------------------------------------------------------------
__global__ void tconv_kernel(const float* __restrict__ W,
                             __half* __restrict__ T, int K, int N)
{
    __shared__ float tile[32][33];
    int n0 = blockIdx.x * 32, k0 = blockIdx.y * 32;
    int tx = threadIdx.x, ty = threadIdx.y;   // 32 x 8
#pragma unroll
    for (int j = 0; j < 32; j += 8)
        tile[ty + j][tx] = W[(size_t)(k0 + ty + j) * N + n0 + tx];
    __syncthreads();
#pragma unroll
    for (int j = 0; j < 32; j += 8)
        T[(size_t)(n0 + ty + j) * K + k0 + tx] = __float2half_rn(tile[tx][ty + j]);
}

// ---------------------------------------------------------------------------
// GEMM geometry: CTA tile 128x128, 128 threads (4 warps @ 64x64), K-chunk 64,
// 3 stages, one barrier/iter, 2 CTAs/SM. Rows 144B (9x16B, conflict-free).
// ---------------------------------------------------------------------------
#define ROWB     144
#define A_B      (128 * ROWB)                // 18432
#define STAGE_B  (256 * ROWB)                // 36864
#define NSTAGE   3
#define SMEM_GEMM (NSTAGE * STAGE_B)         // 110592
#define KC       64
#define NITER    (KDIM / KC)                 // 12

#define GEMM_PRELUDE(Aptr, Bptr)                                               \
    extern __shared__ char sm[];                                               \
    const int tid  = threadIdx.x;                                              \
    const int wid  = tid >> 5;                                                 \
    const int lane = tid & 31;                                                 \
    const size_t m0 = (size_t)blockIdx.y * 128;                                \
    const size_t n0 = (size_t)blockIdx.x * 128;                                \
    const int lr0  = tid >> 3;            /* 0..15 */                          \
    const int lseg = tid & 7;                                                  \
    const uint32_t sbase = smem_u32(sm);                                       \
    const uint32_t dA = sbase + lr0 * ROWB + lseg * 16;                        \
    const uint32_t dB = sbase + A_B + lr0 * ROWB + lseg * 16;                  \
    const __half* sA = (Aptr) + (m0 + lr0) * KDIM + lseg * 8;                  \
    const __half* sB = (Bptr) + (n0 + lr0) * KDIM + lseg * 8;                  \
    auto load_stage = [&](int kc, int s) {                                     \
        _Pragma("unroll")                                                      \
        for (int i = 0; i < 8; i++)                                            \
            CP16(dA + s * STAGE_B + i * 16 * ROWB, sA + kc + (size_t)i * 16 * KDIM); \
        _Pragma("unroll")                                                      \
        for (int i = 0; i < 8; i++)                                            \
            CP16(dB + s * STAGE_B + i * 16 * ROWB, sB + kc + (size_t)i * 16 * KDIM); \
    };                                                                         \
    const int warp_m = wid & 1;                                                \
    const int warp_n = wid >> 1;                                               \
    const int gq  = lane >> 3;                                                 \
    const int r8 = lane & 7;                                                   \
    const uint32_t a_off = (uint32_t)((warp_m * 64 + (gq & 1) * 8 + r8) * ROWB + (gq >> 1) * 16); \
    const uint32_t b_off = (uint32_t)((warp_n * 64 + ((gq >> 1) & 1) * 8 + r8) * ROWB + (gq & 1) * 16); \
    float acc[4][8][4];                                                        \
    _Pragma("unroll")                                                          \
    for (int i = 0; i < 4; i++)                                                \
        _Pragma("unroll")                                                      \
        for (int j = 0; j < 8; j++)                                            \
            _Pragma("unroll")                                                  \
            for (int q = 0; q < 4; q++) acc[i][j][q] = 0.f;                    \
    load_stage(0, 0);  CP_COMMIT();                                            \
    load_stage(KC, 1); CP_COMMIT();                                            \
    for (int it = 0; it < NITER; it++) {                                       \
        CP_WAIT1();                                                            \
        __syncthreads();                                                       \
        if (it + 2 < NITER) load_stage((it + 2) * KC, (it + 2) % NSTAGE);      \
        CP_COMMIT();                                                           \
        const uint32_t st = sbase + (it % NSTAGE) * STAGE_B;                   \
        uint32_t af[2][4][4];                                                  \
        _Pragma("unroll")                                                      \
        for (int mt = 0; mt < 4; mt++)                                         \
            ldsm4(af[0][mt], st + a_off + mt * 16 * ROWB);                     \
        _Pragma("unroll")                                                      \
        for (int kk = 0; kk < 4; kk++) {                                       \
            const uint32_t kb = kk * 32;                                       \
            const int cur = kk & 1;                                            \
            uint32_t bf[8][2], t4[4];                                          \
            _Pragma("unroll")                                                  \
            for (int j = 0; j < 4; j++) {                                      \
                ldsm4(t4, st + A_B + b_off + j * 16 * ROWB + kb);              \
                bf[2 * j + 0][0] = t4[0]; bf[2 * j + 0][1] = t4[1];            \
                bf[2 * j + 1][0] = t4[2]; bf[2 * j + 1][1] = t4[3];            \
            }                                                                  \
            if (kk < 3) {                                                      \
                _Pragma("unroll")                                              \
                for (int mt = 0; mt < 4; mt++)                                 \
                    ldsm4(af[cur ^ 1][mt], st + a_off + mt * 16 * ROWB + kb + 32); \
            }                                                                  \
            _Pragma("unroll")                                                  \
            for (int mt = 0; mt < 4; mt++)                                     \
                _Pragma("unroll")                                              \
                for (int nt = 0; nt < 8; nt++)                                 \
                    mma16816(acc[mt][nt], af[cur][mt], bf[nt]);                \
        }                                                                      \
    }

// ---------------------------------------------------------------------------
// GEMM1: qkv = x @ qkv_w^T, fp16 outputs in XCA layouts.
// ---------------------------------------------------------------------------
__global__ __launch_bounds__(128, 2) void gemm_qkv(
    const __half* __restrict__ A, const __half* __restrict__ B,
    __half* __restrict__ Qt, __half* __restrict__ Kt, __half* __restrict__ Vp)
{
    GEMM_PRELUDE(A, B)

    // ---- epilogue ----
    CP_WAIT0();
    __syncthreads();   // all smem reads done; safe to reuse sm
    const int section = (int)(n0 / 768);   // 0:q 1:k 2:v
    const int crow = warp_m * 64 + (lane >> 2);
    const int ccol = warp_n * 64 + (lane & 3) * 2;

    if (section == 2) {
#pragma unroll
        for (int mt = 0; mt < 4; mt++) {
#pragma unroll
            for (int nt = 0; nt < 8; nt++) {
                size_t row = m0 + crow + mt * 16;
                int vc = (int)(n0 - 1536) + ccol + nt * 8;
                __half2 h0 = __floats2half2_rn(acc[mt][nt][0], acc[mt][nt][1]);
                __half2 h1 = __floats2half2_rn(acc[mt][nt][2], acc[mt][nt][3]);
                *(__half2*)(Vp + row * CH + vc) = h0;
                *(__half2*)(Vp + (row + 8) * CH + vc) = h1;
            }
        }
    } else {
        // transpose through smem: [col 128][token 128], row stride 272B
#pragma unroll
        for (int mt = 0; mt < 4; mt++) {
#pragma unroll
            for (int nt = 0; nt < 8; nt++) {
                int col = ccol + nt * 8;
                int row = crow + mt * 16;
                *(__half*)(sm + (size_t)col * 272 + row * 2)             = __float2half_rn(acc[mt][nt][0]);
                *(__half*)(sm + (size_t)(col + 1) * 272 + row * 2)       = __float2half_rn(acc[mt][nt][1]);
                *(__half*)(sm + (size_t)col * 272 + (row + 8) * 2)       = __float2half_rn(acc[mt][nt][2]);
                *(__half*)(sm + (size_t)(col + 1) * 272 + (row + 8) * 2) = __float2half_rn(acc[mt][nt][3]);
            }
        }
        __syncthreads();
        __half* dst = (section == 0) ? Qt : Kt;
        const int base_gc = (int)n0 - section * 768;
#pragma unroll
        for (int i = 0; i < 16; i++) {
            int idx = tid + i * 128;          // 0..2047
            int col = idx >> 4, tv = idx & 15;
            uint4 val = *(uint4*)(sm + (size_t)col * 272 + tv * 16);
            int gc = base_gc + col;
            int hh = gc / 48, dd = gc - hh * 48;
            size_t tok = m0 + tv * 8;
            int b = (int)(tok / NTOK);
            int n = (int)(tok - (size_t)b * NTOK);
            *(uint4*)(dst + ((size_t)(b * 16 + hh) * HD + dd) * NTOK + n) = val;
        }
    }
}

// ---------------------------------------------------------------------------
// GEMM2: out = att @ proj_w^T + bias, fp32 out.
// ---------------------------------------------------------------------------
__global__ __launch_bounds__(128, 2) void gemm_mma(
    const __half* __restrict__ A, const __half* __restrict__ B,
    float* __restrict__ C, int N, const float* __restrict__ bias)
{
    GEMM_PRELUDE(A, B)

    const int crow = warp_m * 64 + (lane >> 2);
    const int ccol = warp_n * 64 + (lane & 3) * 2;
#pragma unroll
    for (int mt = 0; mt < 4; mt++) {
#pragma unroll
        for (int nt = 0; nt < 8; nt++) {
            float b0 = __ldg(bias + n0 + ccol + nt * 8);
            float b1 = __ldg(bias + n0 + ccol + nt * 8 + 1);
            float2 v0 = {acc[mt][nt][0] + b0, acc[mt][nt][1] + b1};
            float2 v1 = {acc[mt][nt][2] + b0, acc[mt][nt][3] + b1};
            float* p0 = C + (m0 + crow + mt * 16) * (size_t)N + n0 + ccol + nt * 8;
            float* p1 = p0 + 8 * (size_t)N;
            *(float2*)p0 = v0;
            *(float2*)p1 = v1;
        }
    }
}

// ---------------------------------------------------------------------------
// Gram via mma (unchanged from R8/R9).
// ---------------------------------------------------------------------------
#define GROWB  144
#define GTILE  (48 * GROWB)
#define GSTAGE (2 * GTILE)
#define GRED   (2 * GSTAGE)
#define SMEM_GRAM (GRED + 4 * HD * HD * 4)

__global__ __launch_bounds__(256) void gram_kernel()
{
    extern __shared__ char sm[];
    const int tid  = threadIdx.x;
    const int wid  = tid >> 5;
    const int lane = tid & 31;
    const int bh = blockIdx.x;
    const int sp = blockIdx.y;
    const uint32_t sbase = smem_u32(sm);

    const __half* qbase = g_qT + (size_t)bh * HD * NTOK + sp * TOKSP;
    const __half* kbase = g_kT + (size_t)bh * HD * NTOK + sp * TOKSP;

    uint32_t ldst[3];
    const __half* lsrc[3];
#pragma unroll
    for (int i = 0; i < 3; i++) {
        int c = tid + i * 256;
        int cc = (c < 384) ? c : c - 384;
        int r = cc >> 3, seg = cc & 7;
        ldst[i] = sbase + ((c < 384) ? 0 : GTILE) + r * GROWB + seg * 16;
        lsrc[i] = ((c < 384) ? qbase : kbase) + (size_t)r * NTOK + seg * 8;
    }
    auto load_stage = [&](int kc, int s) {
#pragma unroll
        for (int i = 0; i < 3; i++)
            CP16(ldst[i] + s * GSTAGE, lsrc[i] + kc);
    };

    const int g  = lane >> 3;
    const int r8 = lane & 7;
    const uint32_t a_off = (uint32_t)(((g & 1) * 8 + r8) * GROWB + (g >> 1) * 16);
    const uint32_t b_off = (uint32_t)((((g >> 1) & 1) * 8 + r8) * GROWB + (g & 1) * 16);

    float acc[3][6][4];
#pragma unroll
    for (int i = 0; i < 3; i++)
#pragma unroll
        for (int j = 0; j < 6; j++)
#pragma unroll
            for (int q = 0; q < 4; q++) acc[i][j][q] = 0.f;

    const int t2 = ((wid - 4) & 1) * 32 + lane;
    const bool isq = (wid == 4 || wid == 5);
    float nsum = 0.f;

    load_stage(0, 0);
    CP_COMMIT();

    for (int c = 0; c < SPLIT; c++) {
        if (c + 1 < SPLIT) {
            load_stage((c + 1) * 64, (c + 1) & 1);
            CP_COMMIT();
            CP_WAIT1();
        } else {
            CP_WAIT0();
        }
        __syncthreads();
        const uint32_t st = sbase + (c & 1) * GSTAGE;
        if (wid < 4) {
            const uint32_t kb = wid * 32;
            uint32_t af[3][4], bf[6][2];
#pragma unroll
            for (int mt = 0; mt < 3; mt++)
                ldsm4(af[mt], st + a_off + mt * 16 * GROWB + kb);
#pragma unroll
            for (int j = 0; j < 3; j++) {
                uint32_t t4[4];
                ldsm4(t4, st + GTILE + b_off + j * 16 * GROWB + kb);
                bf[j * 2 + 0][0] = t4[0]; bf[j * 2 + 0][1] = t4[1];
                bf[j * 2 + 1][0] = t4[2]; bf[j * 2 + 1][1] = t4[3];
            }
#pragma unroll
            for (int mt = 0; mt < 3; mt++)
#pragma unroll
                for (int nt = 0; nt < 6; nt++)
                    mma16816(acc[mt][nt], af[mt], bf[nt]);
        } else if (t2 < 48) {
            const uint32_t rowaddr = st + (isq ? 0 : GTILE) + t2 * GROWB;
#pragma unroll
            for (int i = 0; i < 32; i++) {
                uint32_t u;
                asm volatile("ld.shared.b32 %0, [%1];" : "=r"(u) : "r"(rowaddr + i * 4));
                float2 f = __half22float2(*(__half2*)&u);
                nsum = fmaf(f.x, f.x, nsum);
                nsum = fmaf(f.y, f.y, nsum);
            }
        }
        __syncthreads();
    }

    if (wid >= 4 && t2 < 48) {
        float* dst = isq ? g_ssq : g_ssk;
        dst[((size_t)bh * SPLIT + sp) * HD + t2] = nsum;
    }

    float* red = (float*)(sm + GRED);
    if (wid < 4) {
        float* rw = red + wid * (HD * HD);
#pragma unroll
        for (int mt = 0; mt < 3; mt++)
#pragma unroll
            for (int nt = 0; nt < 6; nt++) {
                int row = mt * 16 + (lane >> 2);
                int col = nt * 8 + (lane & 3) * 2;
                *(float2*)(rw + row * HD + col) = *(float2*)&acc[mt][nt][0];
                *(float2*)(rw + (row + 8) * HD + col) = *(float2*)&acc[mt][nt][2];
            }
    }
    __syncthreads();
    float* gout = g_gram + ((size_t)bh * SPLIT + sp) * (HD * HD);
#pragma unroll
    for (int i = 0; i < 9; i++) {
        int el = tid + i * 256;
        gout[el] = red[el] + red[HD * HD + el] + red[2 * HD * HD + el] + red[3 * HD * HD + el];
    }
}

// ---------------------------------------------------------------------------
// Softmax (unchanged).
// ---------------------------------------------------------------------------
__global__ __launch_bounds__(256) void softmax_kernel(const float* __restrict__ temperature)
{
    __shared__ float attn[48][52];
    __shared__ float invq[48];
    __shared__ float invk[48];

    const int bh = blockIdx.x;
    const int h = bh & 15;
    const int tid = threadIdx.x;
    const int r = tid >> 4;
    const int c = tid & 15;

    if (tid < 48) {
        float s = 0.f;
#pragma unroll
        for (int p = 0; p < SPLIT; p++)
            s += g_ssq[((size_t)bh * SPLIT + p) * HD + tid];
        invq[tid] = 1.f / fmaxf(sqrtf(s), 1e-12f);
    } else if (tid < 96) {
        float s = 0.f;
#pragma unroll
        for (int p = 0; p < SPLIT; p++)
            s += g_ssk[((size_t)bh * SPLIT + p) * HD + tid - 48];
        invk[tid - 48] = 1.f / fmaxf(sqrtf(s), 1e-12f);
    }

    const float* gin = g_gram + (size_t)bh * SPLIT * (HD * HD);
    float sums[3][3];
#pragma unroll
    for (int i = 0; i < 3; i++)
#pragma unroll
        for (int j = 0; j < 3; j++) {
            float s = 0.f;
            int idx = (3 * r + i) * HD + 3 * c + j;
#pragma unroll
            for (int p = 0; p < SPLIT; p++)
                s += gin[p * (HD * HD) + idx];
            sums[i][j] = s;
        }
    __syncthreads();

    const float temp = temperature[h];
#pragma unroll
    for (int i = 0; i < 3; i++)
#pragma unroll
        for (int j = 0; j < 3; j++)
            attn[3 * r + i][3 * c + j] =
                sums[i][j] * invq[3 * r + i] * invk[3 * c + j] * temp;
    __syncthreads();

    const int lane = tid & 31;
    const int w = tid >> 5;
    for (int d = w; d < 48; d += 8) {
        float x1 = attn[d][lane];
        float x2 = (lane < 16) ? attn[d][32 + lane] : -1e30f;
        float m = fmaxf(x1, x2);
#pragma unroll
        for (int o = 16; o > 0; o >>= 1)
            m = fmaxf(m, __shfl_xor_sync(0xffffffffu, m, o));
        float p1 = expf(x1 - m);
        float p2 = (lane < 16) ? expf(x2 - m) : 0.f;
        float s = p1 + p2;
#pragma unroll
        for (int o = 16; o > 0; o >>= 1)
            s += __shfl_xor_sync(0xffffffffu, s, o);
        float inv = 1.f / s;
        __half* arow = g_attnh + (size_t)bh * (HD * HD) + d * HD;
        arow[lane] = __float2half_rn(p1 * inv);
        if (lane < 16) arow[32 + lane] = __float2half_rn(p2 * inv);
    }
}

// ---------------------------------------------------------------------------
// AV via mma (unchanged).
// ---------------------------------------------------------------------------
#define VROWB  112
#define ATN_B  (48 * VROWB)
#define VSTG   (128 * VROWB)
#define SMEM_AV (ATN_B + 2 * VSTG)

__global__ __launch_bounds__(256) void av_kernel()
{
    extern __shared__ char sm[];
    const int tid  = threadIdx.x;
    const int wid  = tid >> 5;
    const int lane = tid & 31;
    const int bh = blockIdx.x;
    const int sp = blockIdx.y;
    const int b = bh >> 4;
    const int h = bh & 15;
    const uint32_t sbase = smem_u32(sm);
    const uint32_t vs0 = sbase + ATN_B;

    const size_t tokflat = (size_t)b * NTOK + sp * TOKSP;

    for (int idx = tid; idx < 288; idx += 256) {
        int row = idx / 6, seg = idx % 6;
        uint4 val = *(const uint4*)(g_attnh + (size_t)bh * (HD * HD) + row * HD + seg * 8);
        *(uint4*)(sm + row * VROWB + seg * 16) = val;
    }

    int lrow[3], lseg[3];
#pragma unroll
    for (int i = 0; i < 3; i++) {
        int cc = tid + i * 256;
        lrow[i] = cc / 6;
        lseg[i] = cc % 6;
    }
    auto load_stage = [&](int t0, int rows, int s) {
#pragma unroll
        for (int i = 0; i < 3; i++) {
            if (lrow[i] < rows) {
                const __half* src = g_v + (tokflat + t0 + lrow[i]) * CH + h * HD + lseg[i] * 8;
                CP16(vs0 + s * VSTG + lrow[i] * VROWB + lseg[i] * 16, src);
            }
        }
    };

    const int g  = lane >> 3;
    const int r8 = lane & 7;
    const uint32_t a_off = (uint32_t)(((g & 1) * 8 + r8) * VROWB + (g >> 1) * 16);
    const uint32_t b_off = (uint32_t)((((g >> 1) & 1) * 8 + r8) * VROWB + (g & 1) * 16);

    load_stage(0, 128, 0);
    CP_COMMIT();
    __syncthreads();

    uint32_t bf[3][6][2];
#pragma unroll
    for (int k16 = 0; k16 < 3; k16++) {
#pragma unroll
        for (int j = 0; j < 3; j++) {
            uint32_t t4[4];
            ldsm4(t4, sbase + b_off + j * 16 * VROWB + k16 * 32);
            bf[k16][j * 2 + 0][0] = t4[0]; bf[k16][j * 2 + 0][1] = t4[1];
            bf[k16][j * 2 + 1][0] = t4[2]; bf[k16][j * 2 + 1][1] = t4[3];
        }
    }

    const int NIT = (TOKSP + 127) / 128;
    for (int it = 0; it < NIT; it++) {
        const int rows_this = min(128, TOKSP - it * 128);
        if (it + 1 < NIT) {
            load_stage((it + 1) * 128, min(128, TOKSP - (it + 1) * 128), (it + 1) & 1);
            CP_COMMIT();
            CP_WAIT1();
        } else {
            CP_WAIT0();
        }
        __syncthreads();

        if (wid * 16 < rows_this) {
            const uint32_t st = vs0 + (it & 1) * VSTG + wid * 16 * VROWB;
            float acc[6][4];
#pragma unroll
            for (int j = 0; j < 6; j++)
#pragma unroll
                for (int q = 0; q < 4; q++) acc[j][q] = 0.f;
#pragma unroll
            for (int k16 = 0; k16 < 3; k16++) {
                uint32_t af[4];
                ldsm4(af, st + a_off + k16 * 32);
#pragma unroll
                for (int j = 0; j < 6; j++)
                    mma16816(acc[j], af, bf[k16][j]);
            }
            const size_t trow = tokflat + it * 128 + wid * 16 + (lane >> 2);
#pragma unroll
            for (int j = 0; j < 6; j++) {
                int d = j * 8 + (lane & 3) * 2;
                __half2 h0 = __floats2half2_rn(acc[j][0], acc[j][1]);
                __half2 h1 = __floats2half2_rn(acc[j][2], acc[j][3]);
                *(__half2*)(g_ah + trow * CH + h * HD + d) = h0;
                *(__half2*)(g_ah + (trow + 8) * CH + h * HD + d) = h1;
            }
        }
        __syncthreads();
    }
}

// ---------------------------------------------------------------------------
// Launch sequence
// ---------------------------------------------------------------------------
extern "C" void kernel_launch(void* const* d_in, const int* in_sizes, int n_in,
                              void* d_out, int out_size)
{
    const float* x           = (const float*)d_in[0];
    const float* qkv_w       = (const float*)d_in[1];
    const float* temperature = (const float*)d_in[2];
    const float* proj_w      = (const float*)d_in[3];
    const float* proj_b      = (const float*)d_in[4];
    float* out = (float*)d_out;

    __half *xh, *ah, *wq, *wp, *qT, *kT, *vv;
    cudaGetSymbolAddress((void**)&xh, g_xh);
    cudaGetSymbolAddress((void**)&ah, g_ah);
    cudaGetSymbolAddress((void**)&wq, g_wq);
    cudaGetSymbolAddress((void**)&wp, g_wp);
    cudaGetSymbolAddress((void**)&qT, g_qT);
    cudaGetSymbolAddress((void**)&kT, g_kT);
    cudaGetSymbolAddress((void**)&vv, g_v);

    cudaFuncSetAttribute(gemm_qkv, cudaFuncAttributeMaxDynamicSharedMemorySize, SMEM_GEMM);
    cudaFuncSetAttribute(gemm_mma, cudaFuncAttributeMaxDynamicSharedMemorySize, SMEM_GEMM);
    cudaFuncSetAttribute(gram_kernel, cudaFuncAttributeMaxDynamicSharedMemorySize, SMEM_GRAM);
    cudaFuncSetAttribute(av_kernel, cudaFuncAttributeMaxDynamicSharedMemorySize, SMEM_AV);

    int n4 = MROWS * KDIM / 4;
    conv_kernel<<<(n4 + 255) / 256, 256>>>((const float4*)x, (__half2*)xh, n4);

    tconv_kernel<<<dim3((3 * CH) / 32, KDIM / 32), dim3(32, 8)>>>(
        qkv_w, wq, KDIM, 3 * CH);
    tconv_kernel<<<dim3(CH / 32, KDIM / 32), dim3(32, 8)>>>(
        proj_w, wp, KDIM, CH);

    gemm_qkv<<<dim3((3 * CH) / 128, MROWS / 128), 128, SMEM_GEMM>>>(
        xh, wq, qT, kT, vv);

    gram_kernel<<<dim3(BH, SPLIT), 256, SMEM_GRAM>>>();
    softmax_kernel<<<BH, 256>>>(temperature);
    av_kernel<<<dim3(BH, SPLIT), 256, SMEM_AV>>>();

    gemm_mma<<<dim3(CH / 128, MROWS / 128), 128, SMEM_GEMM>>>(
        ah, wp, out, CH, proj_b);
}

// round 12
// speedup vs baseline: 1.1041x; 1.0231x over previous
#include <cuda_runtime.h>
#include <cuda_fp16.h>
#include <math.h>
#include <stdint.h>
#include <stddef.h>

#define BATCH 16
#define NTOK  3136
#define CH    768
#define NH    16
#define HD    48
#define KDIM  768
#define MROWS (BATCH*NTOK)   // 50176
#define BH    (BATCH*NH)     // 256
#define SPLIT 7
#define TOKSP (NTOK/SPLIT)   // 448

// ----------------------------- device scratch ------------------------------
__device__ __half g_xh  [(size_t)MROWS * KDIM];
__device__ __half g_qT  [(size_t)BH * HD * NTOK];   // [bh][d][n] fp16
__device__ __half g_kT  [(size_t)BH * HD * NTOK];
__device__ __half g_v   [(size_t)MROWS * CH];       // [token][h*48+d] fp16
__device__ __half g_ah  [(size_t)MROWS * CH];
__device__ __half g_wq  [(size_t)(3 * CH) * KDIM];
__device__ __half g_wp  [(size_t)CH * KDIM];
__device__ float  g_gram[(size_t)BH * SPLIT * HD * HD];
__device__ float  g_ssq [(size_t)BH * SPLIT * HD];
__device__ float  g_ssk [(size_t)BH * SPLIT * HD];
__device__ __half g_attnh[(size_t)BH * HD * HD];

// ----------------------------- PTX helpers ---------------------------------
__device__ __forceinline__ uint32_t smem_u32(const void* p) {
    return (uint32_t)__cvta_generic_to_shared(p);
}

__device__ __forceinline__ void mma16816(float* c, const uint32_t* a, const uint32_t* b) {
    asm volatile(
        "mma.sync.aligned.m16n8k16.row.col.f32.f16.f16.f32 "
        "{%0,%1,%2,%3}, {%4,%5,%6,%7}, {%8,%9}, {%0,%1,%2,%3};"
        : "+f"(c[0]), "+f"(c[1]), "+f"(c[2]), "+f"(c[3])
        : "r"(a[0]), "r"(a[1]), "r"(a[2]), "r"(a[3]), "r"(b[0]), "r"(b[1]));
}

__device__ __forceinline__ void ldsm4(uint32_t* r, uint32_t addr) {
    asm volatile("ldmatrix.sync.aligned.m8n8.x4.shared.b16 {%0,%1,%2,%3}, [%4];"
        : "=r"(r[0]), "=r"(r[1]), "=r"(r[2]), "=r"(r[3]) : "r"(addr));
}

#define CP16(dst, src) \
    asm volatile("cp.async.cg.shared.global [%0], [%1], 16;" :: "r"(dst), "l"(src))
#define CP_COMMIT()  asm volatile("cp.async.commit_group;" ::: "memory")
#define CP_WAIT0()   asm volatile("cp.async.wait_group 0;" ::: "memory")
#define CP_WAIT1()   asm volatile("cp.async.wait_group 1;" ::: "memory")

// ---------------------------------------------------------------------------
// fp32 -> fp16 convert
// ---------------------------------------------------------------------------
__global__ void conv_kernel(const float4* __restrict__ in,
                            __half2* __restrict__ out, int n4)
{
    int i = blockIdx.x * blockDim.x + threadIdx.x;
    if (i >= n4) return;
    float4 v = in[i];
    out[2 * i + 0] = __floats2half2_rn(v.x, v.y);
    out[2 * i + 1] = __floats2half2_rn(v.z, v.w);
}

// ---------------------------------------------------------------------------
// Transpose + convert: W[K,N] fp32 -> Wt [N,K] fp16
// ---------------------------------------------------------------------------
__global__ void tconv_kernel(const float* __restrict__ W,
                             __half* __restrict__ T, int K, int N)
{
    __shared__ float tile[32][33];
    int n0 = blockIdx.x * 32, k0 = blockIdx.y * 32;
    int tx = threadIdx.x, ty = threadIdx.y;   // 32 x 8
#pragma unroll
    for (int j = 0; j < 32; j += 8)
        tile[ty + j][tx] = W[(size_t)(k0 + ty + j) * N + n0 + tx];
    __syncthreads();
#pragma unroll
    for (int j = 0; j < 32; j += 8)
        T[(size_t)(n0 + ty + j) * K + k0 + tx] = __float2half_rn(tile[tx][ty + j]);
}

// ---------------------------------------------------------------------------
// GEMM geometry: CTA tile 128x128, 128 threads (4 warps @ 64x64), K-chunk 64,
// TWO-stage pipeline (R5 shape, two barriers/iter), 3 CTAs/SM.
// Rows 144B (9x16B, conflict-free). Regs capped for 3-CTA residency.
// ---------------------------------------------------------------------------
#define ROWB     144
#define A_B      (128 * ROWB)                // 18432
#define STAGE_B  (256 * ROWB)                // 36864
#define SMEM_GEMM (2 * STAGE_B)              // 73728
#define KC       64
#define NITER    (KDIM / KC)                 // 12

#define GEMM_PRELUDE(Aptr, Bptr)                                               \
    extern __shared__ char sm[];                                               \
    const int tid  = threadIdx.x;                                              \
    const int wid  = tid >> 5;                                                 \
    const int lane = tid & 31;                                                 \
    const size_t m0 = (size_t)blockIdx.y * 128;                                \
    const size_t n0 = (size_t)blockIdx.x * 128;                                \
    const int lr0  = tid >> 3;            /* 0..15 */                          \
    const int lseg = tid & 7;                                                  \
    const uint32_t sbase = smem_u32(sm);                                       \
    const uint32_t dA = sbase + lr0 * ROWB + lseg * 16;                        \
    const uint32_t dB = sbase + A_B + lr0 * ROWB + lseg * 16;                  \
    const __half* sA = (Aptr) + (m0 + lr0) * KDIM + lseg * 8;                  \
    const __half* sB = (Bptr) + (n0 + lr0) * KDIM + lseg * 8;                  \
    auto load_stage = [&](int kc, int s) {                                     \
        _Pragma("unroll")                                                      \
        for (int i = 0; i < 8; i++)                                            \
            CP16(dA + s * STAGE_B + i * 16 * ROWB, sA + kc + (size_t)i * 16 * KDIM); \
        _Pragma("unroll")                                                      \
        for (int i = 0; i < 8; i++)                                            \
            CP16(dB + s * STAGE_B + i * 16 * ROWB, sB + kc + (size_t)i * 16 * KDIM); \
    };                                                                         \
    const int warp_m = wid & 1;                                                \
    const int warp_n = wid >> 1;                                               \
    const int gq  = lane >> 3;                                                 \
    const int r8 = lane & 7;                                                   \
    const uint32_t a_off = (uint32_t)((warp_m * 64 + (gq & 1) * 8 + r8) * ROWB + (gq >> 1) * 16); \
    const uint32_t b_off = (uint32_t)((warp_n * 64 + ((gq >> 1) & 1) * 8 + r8) * ROWB + (gq & 1) * 16); \
    float acc[4][8][4];                                                        \
    _Pragma("unroll")                                                          \
    for (int i = 0; i < 4; i++)                                                \
        _Pragma("unroll")                                                      \
        for (int j = 0; j < 8; j++)                                            \
            _Pragma("unroll")                                                  \
            for (int q = 0; q < 4; q++) acc[i][j][q] = 0.f;                    \
    load_stage(0, 0);                                                          \
    CP_COMMIT();                                                               \
    for (int it = 0; it < NITER; it++) {                                       \
        const int s = it & 1;                                                  \
        if (it + 1 < NITER) {                                                  \
            load_stage((it + 1) * KC, s ^ 1);                                  \
            CP_COMMIT();                                                       \
            CP_WAIT1();                                                        \
        } else {                                                               \
            CP_WAIT0();                                                        \
        }                                                                      \
        __syncthreads();                                                       \
        const uint32_t st = sbase + s * STAGE_B;                               \
        _Pragma("unroll")                                                      \
        for (int kk = 0; kk < 4; kk++) {                                       \
            const uint32_t kb = kk * 32;                                       \
            uint32_t af[4][4];                                                 \
            _Pragma("unroll")                                                  \
            for (int mt = 0; mt < 4; mt++)                                     \
                ldsm4(af[mt], st + a_off + mt * 16 * ROWB + kb);               \
            _Pragma("unroll")                                                  \
            for (int j2 = 0; j2 < 2; j2++) {                                   \
                uint32_t bf[4][2], t4[4];                                      \
                ldsm4(t4, st + A_B + b_off + (j2 * 2 + 0) * 16 * ROWB + kb);   \
                bf[0][0] = t4[0]; bf[0][1] = t4[1];                            \
                bf[1][0] = t4[2]; bf[1][1] = t4[3];                            \
                ldsm4(t4, st + A_B + b_off + (j2 * 2 + 1) * 16 * ROWB + kb);   \
                bf[2][0] = t4[0]; bf[2][1] = t4[1];                            \
                bf[3][0] = t4[2]; bf[3][1] = t4[3];                            \
                _Pragma("unroll")                                              \
                for (int mt = 0; mt < 4; mt++)                                 \
                    _Pragma("unroll")                                          \
                    for (int nt = 0; nt < 4; nt++)                             \
                        mma16816(acc[mt][j2 * 4 + nt], af[mt], bf[nt]);        \
            }                                                                  \
        }                                                                      \
        __syncthreads();                                                       \
    }

// ---------------------------------------------------------------------------
// GEMM1: qkv = x @ qkv_w^T, fp16 outputs in XCA layouts.
// ---------------------------------------------------------------------------
__global__ __launch_bounds__(128, 3) void gemm_qkv(
    const __half* __restrict__ A, const __half* __restrict__ B,
    __half* __restrict__ Qt, __half* __restrict__ Kt, __half* __restrict__ Vp)
{
    GEMM_PRELUDE(A, B)

    // ---- epilogue ----
    const int section = (int)(n0 / 768);   // 0:q 1:k 2:v
    const int crow = warp_m * 64 + (lane >> 2);
    const int ccol = warp_n * 64 + (lane & 3) * 2;

    if (section == 2) {
#pragma unroll
        for (int mt = 0; mt < 4; mt++) {
#pragma unroll
            for (int nt = 0; nt < 8; nt++) {
                size_t row = m0 + crow + mt * 16;
                int vc = (int)(n0 - 1536) + ccol + nt * 8;
                __half2 h0 = __floats2half2_rn(acc[mt][nt][0], acc[mt][nt][1]);
                __half2 h1 = __floats2half2_rn(acc[mt][nt][2], acc[mt][nt][3]);
                *(__half2*)(Vp + row * CH + vc) = h0;
                *(__half2*)(Vp + (row + 8) * CH + vc) = h1;
            }
        }
    } else {
        // transpose through smem: [col 128][token 128], row stride 272B
#pragma unroll
        for (int mt = 0; mt < 4; mt++) {
#pragma unroll
            for (int nt = 0; nt < 8; nt++) {
                int col = ccol + nt * 8;
                int row = crow + mt * 16;
                *(__half*)(sm + (size_t)col * 272 + row * 2)             = __float2half_rn(acc[mt][nt][0]);
                *(__half*)(sm + (size_t)(col + 1) * 272 + row * 2)       = __float2half_rn(acc[mt][nt][1]);
                *(__half*)(sm + (size_t)col * 272 + (row + 8) * 2)       = __float2half_rn(acc[mt][nt][2]);
                *(__half*)(sm + (size_t)(col + 1) * 272 + (row + 8) * 2) = __float2half_rn(acc[mt][nt][3]);
            }
        }
        __syncthreads();
        __half* dst = (section == 0) ? Qt : Kt;
        const int base_gc = (int)n0 - section * 768;
#pragma unroll
        for (int i = 0; i < 16; i++) {
            int idx = tid + i * 128;          // 0..2047
            int col = idx >> 4, tv = idx & 15;
            uint4 val = *(uint4*)(sm + (size_t)col * 272 + tv * 16);
            int gc = base_gc + col;
            int hh = gc / 48, dd = gc - hh * 48;
            size_t tok = m0 + tv * 8;
            int b = (int)(tok / NTOK);
            int n = (int)(tok - (size_t)b * NTOK);
            *(uint4*)(dst + ((size_t)(b * 16 + hh) * HD + dd) * NTOK + n) = val;
        }
    }
}

// ---------------------------------------------------------------------------
// GEMM2: out = att @ proj_w^T + bias, fp32 out.
// ---------------------------------------------------------------------------
__global__ __launch_bounds__(128, 3) void gemm_mma(
    const __half* __restrict__ A, const __half* __restrict__ B,
    float* __restrict__ C, int N, const float* __restrict__ bias)
{
    GEMM_PRELUDE(A, B)

    const int crow = warp_m * 64 + (lane >> 2);
    const int ccol = warp_n * 64 + (lane & 3) * 2;
#pragma unroll
    for (int mt = 0; mt < 4; mt++) {
#pragma unroll
        for (int nt = 0; nt < 8; nt++) {
            float b0 = __ldg(bias + n0 + ccol + nt * 8);
            float b1 = __ldg(bias + n0 + ccol + nt * 8 + 1);
            float2 v0 = {acc[mt][nt][0] + b0, acc[mt][nt][1] + b1};
            float2 v1 = {acc[mt][nt][2] + b0, acc[mt][nt][3] + b1};
            float* p0 = C + (m0 + crow + mt * 16) * (size_t)N + n0 + ccol + nt * 8;
            float* p1 = p0 + 8 * (size_t)N;
            *(float2*)p0 = v0;
            *(float2*)p1 = v1;
        }
    }
}

// ---------------------------------------------------------------------------
// Gram via mma (unchanged from R8/R9).
// ---------------------------------------------------------------------------
#define GROWB  144
#define GTILE  (48 * GROWB)
#define GSTAGE (2 * GTILE)
#define GRED   (2 * GSTAGE)
#define SMEM_GRAM (GRED + 4 * HD * HD * 4)

__global__ __launch_bounds__(256) void gram_kernel()
{
    extern __shared__ char sm[];
    const int tid  = threadIdx.x;
    const int wid  = tid >> 5;
    const int lane = tid & 31;
    const int bh = blockIdx.x;
    const int sp = blockIdx.y;
    const uint32_t sbase = smem_u32(sm);

    const __half* qbase = g_qT + (size_t)bh * HD * NTOK + sp * TOKSP;
    const __half* kbase = g_kT + (size_t)bh * HD * NTOK + sp * TOKSP;

    uint32_t ldst[3];
    const __half* lsrc[3];
#pragma unroll
    for (int i = 0; i < 3; i++) {
        int c = tid + i * 256;
        int cc = (c < 384) ? c : c - 384;
        int r = cc >> 3, seg = cc & 7;
        ldst[i] = sbase + ((c < 384) ? 0 : GTILE) + r * GROWB + seg * 16;
        lsrc[i] = ((c < 384) ? qbase : kbase) + (size_t)r * NTOK + seg * 8;
    }
    auto load_stage = [&](int kc, int s) {
#pragma unroll
        for (int i = 0; i < 3; i++)
            CP16(ldst[i] + s * GSTAGE, lsrc[i] + kc);
    };

    const int g  = lane >> 3;
    const int r8 = lane & 7;
    const uint32_t a_off = (uint32_t)(((g & 1) * 8 + r8) * GROWB + (g >> 1) * 16);
    const uint32_t b_off = (uint32_t)((((g >> 1) & 1) * 8 + r8) * GROWB + (g & 1) * 16);

    float acc[3][6][4];
#pragma unroll
    for (int i = 0; i < 3; i++)
#pragma unroll
        for (int j = 0; j < 6; j++)
#pragma unroll
            for (int q = 0; q < 4; q++) acc[i][j][q] = 0.f;

    const int t2 = ((wid - 4) & 1) * 32 + lane;
    const bool isq = (wid == 4 || wid == 5);
    float nsum = 0.f;

    load_stage(0, 0);
    CP_COMMIT();

    for (int c = 0; c < SPLIT; c++) {
        if (c + 1 < SPLIT) {
            load_stage((c + 1) * 64, (c + 1) & 1);
            CP_COMMIT();
            CP_WAIT1();
        } else {
            CP_WAIT0();
        }
        __syncthreads();
        const uint32_t st = sbase + (c & 1) * GSTAGE;
        if (wid < 4) {
            const uint32_t kb = wid * 32;
            uint32_t af[3][4], bf[6][2];
#pragma unroll
            for (int mt = 0; mt < 3; mt++)
                ldsm4(af[mt], st + a_off + mt * 16 * GROWB + kb);
#pragma unroll
            for (int j = 0; j < 3; j++) {
                uint32_t t4[4];
                ldsm4(t4, st + GTILE + b_off + j * 16 * GROWB + kb);
                bf[j * 2 + 0][0] = t4[0]; bf[j * 2 + 0][1] = t4[1];
                bf[j * 2 + 1][0] = t4[2]; bf[j * 2 + 1][1] = t4[3];
            }
#pragma unroll
            for (int mt = 0; mt < 3; mt++)
#pragma unroll
                for (int nt = 0; nt < 6; nt++)
                    mma16816(acc[mt][nt], af[mt], bf[nt]);
        } else if (t2 < 48) {
            const uint32_t rowaddr = st + (isq ? 0 : GTILE) + t2 * GROWB;
#pragma unroll
            for (int i = 0; i < 32; i++) {
                uint32_t u;
                asm volatile("ld.shared.b32 %0, [%1];" : "=r"(u) : "r"(rowaddr + i * 4));
                float2 f = __half22float2(*(__half2*)&u);
                nsum = fmaf(f.x, f.x, nsum);
                nsum = fmaf(f.y, f.y, nsum);
            }
        }
        __syncthreads();
    }

    if (wid >= 4 && t2 < 48) {
        float* dst = isq ? g_ssq : g_ssk;
        dst[((size_t)bh * SPLIT + sp) * HD + t2] = nsum;
    }

    float* red = (float*)(sm + GRED);
    if (wid < 4) {
        float* rw = red + wid * (HD * HD);
#pragma unroll
        for (int mt = 0; mt < 3; mt++)
#pragma unroll
            for (int nt = 0; nt < 6; nt++) {
                int row = mt * 16 + (lane >> 2);
                int col = nt * 8 + (lane & 3) * 2;
                *(float2*)(rw + row * HD + col) = *(float2*)&acc[mt][nt][0];
                *(float2*)(rw + (row + 8) * HD + col) = *(float2*)&acc[mt][nt][2];
            }
    }
    __syncthreads();
    float* gout = g_gram + ((size_t)bh * SPLIT + sp) * (HD * HD);
#pragma unroll
    for (int i = 0; i < 9; i++) {
        int el = tid + i * 256;
        gout[el] = red[el] + red[HD * HD + el] + red[2 * HD * HD + el] + red[3 * HD * HD + el];
    }
}

// ---------------------------------------------------------------------------
// Softmax (unchanged).
// ---------------------------------------------------------------------------
__global__ __launch_bounds__(256) void softmax_kernel(const float* __restrict__ temperature)
{
    __shared__ float attn[48][52];
    __shared__ float invq[48];
    __shared__ float invk[48];

    const int bh = blockIdx.x;
    const int h = bh & 15;
    const int tid = threadIdx.x;
    const int r = tid >> 4;
    const int c = tid & 15;

    if (tid < 48) {
        float s = 0.f;
#pragma unroll
        for (int p = 0; p < SPLIT; p++)
            s += g_ssq[((size_t)bh * SPLIT + p) * HD + tid];
        invq[tid] = 1.f / fmaxf(sqrtf(s), 1e-12f);
    } else if (tid < 96) {
        float s = 0.f;
#pragma unroll
        for (int p = 0; p < SPLIT; p++)
            s += g_ssk[((size_t)bh * SPLIT + p) * HD + tid - 48];
        invk[tid - 48] = 1.f / fmaxf(sqrtf(s), 1e-12f);
    }

    const float* gin = g_gram + (size_t)bh * SPLIT * (HD * HD);
    float sums[3][3];
#pragma unroll
    for (int i = 0; i < 3; i++)
#pragma unroll
        for (int j = 0; j < 3; j++) {
            float s = 0.f;
            int idx = (3 * r + i) * HD + 3 * c + j;
#pragma unroll
            for (int p = 0; p < SPLIT; p++)
                s += gin[p * (HD * HD) + idx];
            sums[i][j] = s;
        }
    __syncthreads();

    const float temp = temperature[h];
#pragma unroll
    for (int i = 0; i < 3; i++)
#pragma unroll
        for (int j = 0; j < 3; j++)
            attn[3 * r + i][3 * c + j] =
                sums[i][j] * invq[3 * r + i] * invk[3 * c + j] * temp;
    __syncthreads();

    const int lane = tid & 31;
    const int w = tid >> 5;
    for (int d = w; d < 48; d += 8) {
        float x1 = attn[d][lane];
        float x2 = (lane < 16) ? attn[d][32 + lane] : -1e30f;
        float m = fmaxf(x1, x2);
#pragma unroll
        for (int o = 16; o > 0; o >>= 1)
            m = fmaxf(m, __shfl_xor_sync(0xffffffffu, m, o));
        float p1 = expf(x1 - m);
        float p2 = (lane < 16) ? expf(x2 - m) : 0.f;
        float s = p1 + p2;
#pragma unroll
        for (int o = 16; o > 0; o >>= 1)
            s += __shfl_xor_sync(0xffffffffu, s, o);
        float inv = 1.f / s;
        __half* arow = g_attnh + (size_t)bh * (HD * HD) + d * HD;
        arow[lane] = __float2half_rn(p1 * inv);
        if (lane < 16) arow[32 + lane] = __float2half_rn(p2 * inv);
    }
}

// ---------------------------------------------------------------------------
// AV via mma (unchanged).
// ---------------------------------------------------------------------------
#define VROWB  112
#define ATN_B  (48 * VROWB)
#define VSTG   (128 * VROWB)
#define SMEM_AV (ATN_B + 2 * VSTG)

__global__ __launch_bounds__(256) void av_kernel()
{
    extern __shared__ char sm[];
    const int tid  = threadIdx.x;
    const int wid  = tid >> 5;
    const int lane = tid & 31;
    const int bh = blockIdx.x;
    const int sp = blockIdx.y;
    const int b = bh >> 4;
    const int h = bh & 15;
    const uint32_t sbase = smem_u32(sm);
    const uint32_t vs0 = sbase + ATN_B;

    const size_t tokflat = (size_t)b * NTOK + sp * TOKSP;

    for (int idx = tid; idx < 288; idx += 256) {
        int row = idx / 6, seg = idx % 6;
        uint4 val = *(const uint4*)(g_attnh + (size_t)bh * (HD * HD) + row * HD + seg * 8);
        *(uint4*)(sm + row * VROWB + seg * 16) = val;
    }

    int lrow[3], lseg[3];
#pragma unroll
    for (int i = 0; i < 3; i++) {
        int cc = tid + i * 256;
        lrow[i] = cc / 6;
        lseg[i] = cc % 6;
    }
    auto load_stage = [&](int t0, int rows, int s) {
#pragma unroll
        for (int i = 0; i < 3; i++) {
            if (lrow[i] < rows) {
                const __half* src = g_v + (tokflat + t0 + lrow[i]) * CH + h * HD + lseg[i] * 8;
                CP16(vs0 + s * VSTG + lrow[i] * VROWB + lseg[i] * 16, src);
            }
        }
    };

    const int g  = lane >> 3;
    const int r8 = lane & 7;
    const uint32_t a_off = (uint32_t)(((g & 1) * 8 + r8) * VROWB + (g >> 1) * 16);
    const uint32_t b_off = (uint32_t)((((g >> 1) & 1) * 8 + r8) * VROWB + (g & 1) * 16);

    load_stage(0, 128, 0);
    CP_COMMIT();
    __syncthreads();

    uint32_t bf[3][6][2];
#pragma unroll
    for (int k16 = 0; k16 < 3; k16++) {
#pragma unroll
        for (int j = 0; j < 3; j++) {
            uint32_t t4[4];
            ldsm4(t4, sbase + b_off + j * 16 * VROWB + k16 * 32);
            bf[k16][j * 2 + 0][0] = t4[0]; bf[k16][j * 2 + 0][1] = t4[1];
            bf[k16][j * 2 + 1][0] = t4[2]; bf[k16][j * 2 + 1][1] = t4[3];
        }
    }

    const int NIT = (TOKSP + 127) / 128;
    for (int it = 0; it < NIT; it++) {
        const int rows_this = min(128, TOKSP - it * 128);
        if (it + 1 < NIT) {
            load_stage((it + 1) * 128, min(128, TOKSP - (it + 1) * 128), (it + 1) & 1);
            CP_COMMIT();
            CP_WAIT1();
        } else {
            CP_WAIT0();
        }
        __syncthreads();

        if (wid * 16 < rows_this) {
            const uint32_t st = vs0 + (it & 1) * VSTG + wid * 16 * VROWB;
            float acc[6][4];
#pragma unroll
            for (int j = 0; j < 6; j++)
#pragma unroll
                for (int q = 0; q < 4; q++) acc[j][q] = 0.f;
#pragma unroll
            for (int k16 = 0; k16 < 3; k16++) {
                uint32_t af[4];
                ldsm4(af, st + a_off + k16 * 32);
#pragma unroll
                for (int j = 0; j < 6; j++)
                    mma16816(acc[j], af, bf[k16][j]);
            }
            const size_t trow = tokflat + it * 128 + wid * 16 + (lane >> 2);
#pragma unroll
            for (int j = 0; j < 6; j++) {
                int d = j * 8 + (lane & 3) * 2;
                __half2 h0 = __floats2half2_rn(acc[j][0], acc[j][1]);
                __half2 h1 = __floats2half2_rn(acc[j][2], acc[j][3]);
                *(__half2*)(g_ah + trow * CH + h * HD + d) = h0;
                *(__half2*)(g_ah + (trow + 8) * CH + h * HD + d) = h1;
            }
        }
        __syncthreads();
    }
}

// ---------------------------------------------------------------------------
// Launch sequence
// ---------------------------------------------------------------------------
extern "C" void kernel_launch(void* const* d_in, const int* in_sizes, int n_in,
                              void* d_out, int out_size)
{
    const float* x           = (const float*)d_in[0];
    const float* qkv_w       = (const float*)d_in[1];
    const float* temperature = (const float*)d_in[2];
    const float* proj_w      = (const float*)d_in[3];
    const float* proj_b      = (const float*)d_in[4];
    float* out = (float*)d_out;

    __half *xh, *ah, *wq, *wp, *qT, *kT, *vv;
    cudaGetSymbolAddress((void**)&xh, g_xh);
    cudaGetSymbolAddress((void**)&ah, g_ah);
    cudaGetSymbolAddress((void**)&wq, g_wq);
    cudaGetSymbolAddress((void**)&wp, g_wp);
    cudaGetSymbolAddress((void**)&qT, g_qT);
    cudaGetSymbolAddress((void**)&kT, g_kT);
    cudaGetSymbolAddress((void**)&vv, g_v);

    cudaFuncSetAttribute(gemm_qkv, cudaFuncAttributeMaxDynamicSharedMemorySize, SMEM_GEMM);
    cudaFuncSetAttribute(gemm_mma, cudaFuncAttributeMaxDynamicSharedMemorySize, SMEM_GEMM);
    cudaFuncSetAttribute(gram_kernel, cudaFuncAttributeMaxDynamicSharedMemorySize, SMEM_GRAM);
    cudaFuncSetAttribute(av_kernel, cudaFuncAttributeMaxDynamicSharedMemorySize, SMEM_AV);

    int n4 = MROWS * KDIM / 4;
    conv_kernel<<<(n4 + 255) / 256, 256>>>((const float4*)x, (__half2*)xh, n4);

    tconv_kernel<<<dim3((3 * CH) / 32, KDIM / 32), dim3(32, 8)>>>(
        qkv_w, wq, KDIM, 3 * CH);
    tconv_kernel<<<dim3(CH / 32, KDIM / 32), dim3(32, 8)>>>(
        proj_w, wp, KDIM, CH);

    gemm_qkv<<<dim3((3 * CH) / 128, MROWS / 128), 128, SMEM_GEMM>>>(
        xh, wq, qT, kT, vv);

    gram_kernel<<<dim3(BH, SPLIT), 256, SMEM_GRAM>>>();
    softmax_kernel<<<BH, 256>>>(temperature);
    av_kernel<<<dim3(BH, SPLIT), 256, SMEM_AV>>>();

    gemm_mma<<<dim3(CH / 128, MROWS / 128), 128, SMEM_GEMM>>>(
        ah, wp, out, CH, proj_b);
}

// round 14
// speedup vs baseline: 1.1070x; 1.0026x over previous
#include <cuda_runtime.h>
#include <cuda_fp16.h>
#include <math.h>
#include <stdint.h>
#include <stddef.h>

#define BATCH 16
#define NTOK  3136
#define CH    768
#define NH    16
#define HD    48
#define KDIM  768
#define MROWS (BATCH*NTOK)   // 50176
#define BH    (BATCH*NH)     // 256
#define SPLIT 7
#define TOKSP (NTOK/SPLIT)   // 448

// ----------------------------- device scratch ------------------------------
__device__ __half g_xh  [(size_t)MROWS * KDIM];
__device__ __half g_qT  [(size_t)BH * HD * NTOK];   // [bh][d][n] fp16
__device__ __half g_kT  [(size_t)BH * HD * NTOK];
__device__ __half g_v   [(size_t)MROWS * CH];       // [token][h*48+d] fp16
__device__ __half g_ah  [(size_t)MROWS * CH];
__device__ __half g_wq  [(size_t)(3 * CH) * KDIM];
__device__ __half g_wp  [(size_t)CH * KDIM];
__device__ float  g_gram[(size_t)BH * SPLIT * HD * HD];
__device__ float  g_ssq [(size_t)BH * SPLIT * HD];
__device__ float  g_ssk [(size_t)BH * SPLIT * HD];
__device__ __half g_attnh[(size_t)BH * HD * HD];

// ----------------------------- PTX helpers ---------------------------------
__device__ __forceinline__ uint32_t smem_u32(const void* p) {
    return (uint32_t)__cvta_generic_to_shared(p);
}

__device__ __forceinline__ void mma16816(float* c, const uint32_t* a, const uint32_t* b) {
    asm volatile(
        "mma.sync.aligned.m16n8k16.row.col.f32.f16.f16.f32 "
        "{%0,%1,%2,%3}, {%4,%5,%6,%7}, {%8,%9}, {%0,%1,%2,%3};"
        : "+f"(c[0]), "+f"(c[1]), "+f"(c[2]), "+f"(c[3])
        : "r"(a[0]), "r"(a[1]), "r"(a[2]), "r"(a[3]), "r"(b[0]), "r"(b[1]));
}

__device__ __forceinline__ void ldsm4(uint32_t* r, uint32_t addr) {
    asm volatile("ldmatrix.sync.aligned.m8n8.x4.shared.b16 {%0,%1,%2,%3}, [%4];"
        : "=r"(r[0]), "=r"(r[1]), "=r"(r[2]), "=r"(r[3]) : "r"(addr));
}

#define CP16(dst, src) \
    asm volatile("cp.async.cg.shared.global [%0], [%1], 16;" :: "r"(dst), "l"(src))
#define CP_COMMIT()  asm volatile("cp.async.commit_group;" ::: "memory")
#define CP_WAIT0()   asm volatile("cp.async.wait_group 0;" ::: "memory")
#define CP_WAIT1()   asm volatile("cp.async.wait_group 1;" ::: "memory")

// ---------------------------------------------------------------------------
// fp32 -> fp16 convert
// ---------------------------------------------------------------------------
__global__ void conv_kernel(const float4* __restrict__ in,
                            __half2* __restrict__ out, int n4)
{
    int i = blockIdx.x * blockDim.x + threadIdx.x;
    if (i >= n4) return;
    float4 v = in[i];
    out[2 * i + 0] = __floats2half2_rn(v.x, v.y);
    out[2 * i + 1] = __floats2half2_rn(v.z, v.w);
}

// ---------------------------------------------------------------------------
// Transpose + convert: W[K,N] fp32 -> Wt [N,K] fp16
// ---------------------------------------------------------------------------
__global__ void tconv_kernel(const float* __restrict__ W,
                             __half* __restrict__ T, int K, int N)
{
    __shared__ float tile[32][33];
    int n0 = blockIdx.x * 32, k0 = blockIdx.y * 32;
    int tx = threadIdx.x, ty = threadIdx.y;   // 32 x 8
#pragma unroll
    for (int j = 0; j < 32; j += 8)
        tile[ty + j][tx] = W[(size_t)(k0 + ty + j) * N + n0 + tx];
    __syncthreads();
#pragma unroll
    for (int j = 0; j < 32; j += 8)
        T[(size_t)(n0 + ty + j) * K + k0 + tx] = __float2half_rn(tile[tx][ty + j]);
}

// ---------------------------------------------------------------------------
// GEMM geometry: CTA tile 128x128, 128 threads (4 warps @ 64x64), K-chunk 64,
// 2-stage pipeline, ONE barrier per iteration (wait -> sync -> load order:
// sync AFTER wait gives CTA-wide visibility of the cp.async data AND frees
// the stage read in the previous iteration). 3 CTAs/SM. Rows 144B.
// ---------------------------------------------------------------------------
#define ROWB     144
#define A_B      (128 * ROWB)                // 18432
#define STAGE_B  (256 * ROWB)                // 36864
#define SMEM_GEMM (2 * STAGE_B)              // 73728
#define KC       64
#define NITER    (KDIM / KC)                 // 12

#define GEMM_PRELUDE(Aptr, Bptr)                                               \
    extern __shared__ char sm[];                                               \
    const int tid  = threadIdx.x;                                              \
    const int wid  = tid >> 5;                                                 \
    const int lane = tid & 31;                                                 \
    const size_t m0 = (size_t)blockIdx.y * 128;                                \
    const size_t n0 = (size_t)blockIdx.x * 128;                                \
    const int lr0  = tid >> 3;            /* 0..15 */                          \
    const int lseg = tid & 7;                                                  \
    const uint32_t sbase = smem_u32(sm);                                       \
    const uint32_t dA = sbase + lr0 * ROWB + lseg * 16;                        \
    const uint32_t dB = sbase + A_B + lr0 * ROWB + lseg * 16;                  \
    const __half* sA = (Aptr) + (m0 + lr0) * KDIM + lseg * 8;                  \
    const __half* sB = (Bptr) + (n0 + lr0) * KDIM + lseg * 8;                  \
    auto load_stage = [&](int kc, int s) {                                     \
        _Pragma("unroll")                                                      \
        for (int i = 0; i < 8; i++)                                            \
            CP16(dA + s * STAGE_B + i * 16 * ROWB, sA + kc + (size_t)i * 16 * KDIM); \
        _Pragma("unroll")                                                      \
        for (int i = 0; i < 8; i++)                                            \
            CP16(dB + s * STAGE_B + i * 16 * ROWB, sB + kc + (size_t)i * 16 * KDIM); \
    };                                                                         \
    const int warp_m = wid & 1;                                                \
    const int warp_n = wid >> 1;                                               \
    const int gq  = lane >> 3;                                                 \
    const int r8 = lane & 7;                                                   \
    const uint32_t a_off = (uint32_t)((warp_m * 64 + (gq & 1) * 8 + r8) * ROWB + (gq >> 1) * 16); \
    const uint32_t b_off = (uint32_t)((warp_n * 64 + ((gq >> 1) & 1) * 8 + r8) * ROWB + (gq & 1) * 16); \
    float acc[4][8][4];                                                        \
    _Pragma("unroll")                                                          \
    for (int i = 0; i < 4; i++)                                                \
        _Pragma("unroll")                                                      \
        for (int j = 0; j < 8; j++)                                            \
            _Pragma("unroll")                                                  \
            for (int q = 0; q < 4; q++) acc[i][j][q] = 0.f;                    \
    load_stage(0, 0);                                                          \
    CP_COMMIT();                                                               \
    for (int it = 0; it < NITER; it++) {                                       \
        const int s = it & 1;                                                  \
        CP_WAIT0();                   /* load(it) retired (issued last iter) */ \
        __syncthreads();              /* stage s visible CTA-wide; s^1 free */ \
        if (it + 1 < NITER) {                                                  \
            load_stage((it + 1) * KC, s ^ 1);                                  \
            CP_COMMIT();                                                       \
        }                                                                      \
        const uint32_t st = sbase + s * STAGE_B;                               \
        _Pragma("unroll")                                                      \
        for (int kk = 0; kk < 4; kk++) {                                       \
            const uint32_t kb = kk * 32;                                       \
            uint32_t af[4][4];                                                 \
            _Pragma("unroll")                                                  \
            for (int mt = 0; mt < 4; mt++)                                     \
                ldsm4(af[mt], st + a_off + mt * 16 * ROWB + kb);               \
            _Pragma("unroll")                                                  \
            for (int j2 = 0; j2 < 2; j2++) {                                   \
                uint32_t bf[4][2], t4[4];                                      \
                ldsm4(t4, st + A_B + b_off + (j2 * 2 + 0) * 16 * ROWB + kb);   \
                bf[0][0] = t4[0]; bf[0][1] = t4[1];                            \
                bf[1][0] = t4[2]; bf[1][1] = t4[3];                            \
                ldsm4(t4, st + A_B + b_off + (j2 * 2 + 1) * 16 * ROWB + kb);   \
                bf[2][0] = t4[0]; bf[2][1] = t4[1];                            \
                bf[3][0] = t4[2]; bf[3][1] = t4[3];                            \
                _Pragma("unroll")                                              \
                for (int mt = 0; mt < 4; mt++)                                 \
                    _Pragma("unroll")                                          \
                    for (int nt = 0; nt < 4; nt++)                             \
                        mma16816(acc[mt][j2 * 4 + nt], af[mt], bf[nt]);        \
            }                                                                  \
        }                                                                      \
    }

// ---------------------------------------------------------------------------
// GEMM1: qkv = x @ qkv_w^T, fp16 outputs in XCA layouts.
// ---------------------------------------------------------------------------
__global__ __launch_bounds__(128, 3) void gemm_qkv(
    const __half* __restrict__ A, const __half* __restrict__ B,
    __half* __restrict__ Qt, __half* __restrict__ Kt, __half* __restrict__ Vp)
{
    GEMM_PRELUDE(A, B)

    // ---- epilogue ----
    const int section = (int)(n0 / 768);   // 0:q 1:k 2:v
    const int crow = warp_m * 64 + (lane >> 2);
    const int ccol = warp_n * 64 + (lane & 3) * 2;

    if (section == 2) {
#pragma unroll
        for (int mt = 0; mt < 4; mt++) {
#pragma unroll
            for (int nt = 0; nt < 8; nt++) {
                size_t row = m0 + crow + mt * 16;
                int vc = (int)(n0 - 1536) + ccol + nt * 8;
                __half2 h0 = __floats2half2_rn(acc[mt][nt][0], acc[mt][nt][1]);
                __half2 h1 = __floats2half2_rn(acc[mt][nt][2], acc[mt][nt][3]);
                *(__half2*)(Vp + row * CH + vc) = h0;
                *(__half2*)(Vp + (row + 8) * CH + vc) = h1;
            }
        }
    } else {
        __syncthreads();   // all warps done reading final stage before reuse
        // transpose through smem: [col 128][token 128], row stride 272B
#pragma unroll
        for (int mt = 0; mt < 4; mt++) {
#pragma unroll
            for (int nt = 0; nt < 8; nt++) {
                int col = ccol + nt * 8;
                int row = crow + mt * 16;
                *(__half*)(sm + (size_t)col * 272 + row * 2)             = __float2half_rn(acc[mt][nt][0]);
                *(__half*)(sm + (size_t)(col + 1) * 272 + row * 2)       = __float2half_rn(acc[mt][nt][1]);
                *(__half*)(sm + (size_t)col * 272 + (row + 8) * 2)       = __float2half_rn(acc[mt][nt][2]);
                *(__half*)(sm + (size_t)(col + 1) * 272 + (row + 8) * 2) = __float2half_rn(acc[mt][nt][3]);
            }
        }
        __syncthreads();
        __half* dst = (section == 0) ? Qt : Kt;
        const int base_gc = (int)n0 - section * 768;
#pragma unroll
        for (int i = 0; i < 16; i++) {
            int idx = tid + i * 128;          // 0..2047
            int col = idx >> 4, tv = idx & 15;
            uint4 val = *(uint4*)(sm + (size_t)col * 272 + tv * 16);
            int gc = base_gc + col;
            int hh = gc / 48, dd = gc - hh * 48;
            size_t tok = m0 + tv * 8;
            int b = (int)(tok / NTOK);
            int n = (int)(tok - (size_t)b * NTOK);
            *(uint4*)(dst + ((size_t)(b * 16 + hh) * HD + dd) * NTOK + n) = val;
        }
    }
}

// ---------------------------------------------------------------------------
// GEMM2: out = att @ proj_w^T + bias, fp32 out.
// ---------------------------------------------------------------------------
__global__ __launch_bounds__(128, 3) void gemm_mma(
    const __half* __restrict__ A, const __half* __restrict__ B,
    float* __restrict__ C, int N, const float* __restrict__ bias)
{
    GEMM_PRELUDE(A, B)

    const int crow = warp_m * 64 + (lane >> 2);
    const int ccol = warp_n * 64 + (lane & 3) * 2;
#pragma unroll
    for (int mt = 0; mt < 4; mt++) {
#pragma unroll
        for (int nt = 0; nt < 8; nt++) {
            float b0 = __ldg(bias + n0 + ccol + nt * 8);
            float b1 = __ldg(bias + n0 + ccol + nt * 8 + 1);
            float2 v0 = {acc[mt][nt][0] + b0, acc[mt][nt][1] + b1};
            float2 v1 = {acc[mt][nt][2] + b0, acc[mt][nt][3] + b1};
            float* p0 = C + (m0 + crow + mt * 16) * (size_t)N + n0 + ccol + nt * 8;
            float* p1 = p0 + 8 * (size_t)N;
            *(float2*)p0 = v0;
            *(float2*)p1 = v1;
        }
    }
}

// ---------------------------------------------------------------------------
// Gram via mma: one barrier per chunk (wait -> sync -> load order).
// ---------------------------------------------------------------------------
#define GROWB  144
#define GTILE  (48 * GROWB)
#define GSTAGE (2 * GTILE)
#define GRED   (2 * GSTAGE)
#define SMEM_GRAM (GRED + 4 * HD * HD * 4)

__global__ __launch_bounds__(256) void gram_kernel()
{
    extern __shared__ char sm[];
    const int tid  = threadIdx.x;
    const int wid  = tid >> 5;
    const int lane = tid & 31;
    const int bh = blockIdx.x;
    const int sp = blockIdx.y;
    const uint32_t sbase = smem_u32(sm);

    const __half* qbase = g_qT + (size_t)bh * HD * NTOK + sp * TOKSP;
    const __half* kbase = g_kT + (size_t)bh * HD * NTOK + sp * TOKSP;

    uint32_t ldst[3];
    const __half* lsrc[3];
#pragma unroll
    for (int i = 0; i < 3; i++) {
        int c = tid + i * 256;
        int cc = (c < 384) ? c : c - 384;
        int r = cc >> 3, seg = cc & 7;
        ldst[i] = sbase + ((c < 384) ? 0 : GTILE) + r * GROWB + seg * 16;
        lsrc[i] = ((c < 384) ? qbase : kbase) + (size_t)r * NTOK + seg * 8;
    }
    auto load_stage = [&](int kc, int s) {
#pragma unroll
        for (int i = 0; i < 3; i++)
            CP16(ldst[i] + s * GSTAGE, lsrc[i] + kc);
    };

    const int g  = lane >> 3;
    const int r8 = lane & 7;
    const uint32_t a_off = (uint32_t)(((g & 1) * 8 + r8) * GROWB + (g >> 1) * 16);
    const uint32_t b_off = (uint32_t)((((g >> 1) & 1) * 8 + r8) * GROWB + (g & 1) * 16);

    float acc[3][6][4];
#pragma unroll
    for (int i = 0; i < 3; i++)
#pragma unroll
        for (int j = 0; j < 6; j++)
#pragma unroll
            for (int q = 0; q < 4; q++) acc[i][j][q] = 0.f;

    const int t2 = ((wid - 4) & 1) * 32 + lane;
    const bool isq = (wid == 4 || wid == 5);
    float nsum = 0.f;

    load_stage(0, 0);
    CP_COMMIT();

    for (int c = 0; c < SPLIT; c++) {
        CP_WAIT0();                    // stage c retired (mine)
        __syncthreads();               // visible CTA-wide; stage c^1 free
        if (c + 1 < SPLIT) {
            load_stage((c + 1) * 64, (c + 1) & 1);
            CP_COMMIT();
        }
        const uint32_t st = sbase + (c & 1) * GSTAGE;
        if (wid < 4) {
            const uint32_t kb = wid * 32;
            uint32_t af[3][4], bf[6][2];
#pragma unroll
            for (int mt = 0; mt < 3; mt++)
                ldsm4(af[mt], st + a_off + mt * 16 * GROWB + kb);
#pragma unroll
            for (int j = 0; j < 3; j++) {
                uint32_t t4[4];
                ldsm4(t4, st + GTILE + b_off + j * 16 * GROWB + kb);
                bf[j * 2 + 0][0] = t4[0]; bf[j * 2 + 0][1] = t4[1];
                bf[j * 2 + 1][0] = t4[2]; bf[j * 2 + 1][1] = t4[3];
            }
#pragma unroll
            for (int mt = 0; mt < 3; mt++)
#pragma unroll
                for (int nt = 0; nt < 6; nt++)
                    mma16816(acc[mt][nt], af[mt], bf[nt]);
        } else if (t2 < 48) {
            const uint32_t rowaddr = st + (isq ? 0 : GTILE) + t2 * GROWB;
#pragma unroll
            for (int i = 0; i < 32; i++) {
                uint32_t u;
                asm volatile("ld.shared.b32 %0, [%1];" : "=r"(u) : "r"(rowaddr + i * 4));
                float2 f = __half22float2(*(__half2*)&u);
                nsum = fmaf(f.x, f.x, nsum);
                nsum = fmaf(f.y, f.y, nsum);
            }
        }
    }

    if (wid >= 4 && t2 < 48) {
        float* dst = isq ? g_ssq : g_ssk;
        dst[((size_t)bh * SPLIT + sp) * HD + t2] = nsum;
    }

    __syncthreads();
    float* red = (float*)(sm + GRED);
    if (wid < 4) {
        float* rw = red + wid * (HD * HD);
#pragma unroll
        for (int mt = 0; mt < 3; mt++)
#pragma unroll
            for (int nt = 0; nt < 6; nt++) {
                int row = mt * 16 + (lane >> 2);
                int col = nt * 8 + (lane & 3) * 2;
                *(float2*)(rw + row * HD + col) = *(float2*)&acc[mt][nt][0];
                *(float2*)(rw + (row + 8) * HD + col) = *(float2*)&acc[mt][nt][2];
            }
    }
    __syncthreads();
    float* gout = g_gram + ((size_t)bh * SPLIT + sp) * (HD * HD);
#pragma unroll
    for (int i = 0; i < 9; i++) {
        int el = tid + i * 256;
        gout[el] = red[el] + red[HD * HD + el] + red[2 * HD * HD + el] + red[3 * HD * HD + el];
    }
}

// ---------------------------------------------------------------------------
// Softmax (unchanged).
// ---------------------------------------------------------------------------
__global__ __launch_bounds__(256) void softmax_kernel(const float* __restrict__ temperature)
{
    __shared__ float attn[48][52];
    __shared__ float invq[48];
    __shared__ float invk[48];

    const int bh = blockIdx.x;
    const int h = bh & 15;
    const int tid = threadIdx.x;
    const int r = tid >> 4;
    const int c = tid & 15;

    if (tid < 48) {
        float s = 0.f;
#pragma unroll
        for (int p = 0; p < SPLIT; p++)
            s += g_ssq[((size_t)bh * SPLIT + p) * HD + tid];
        invq[tid] = 1.f / fmaxf(sqrtf(s), 1e-12f);
    } else if (tid < 96) {
        float s = 0.f;
#pragma unroll
        for (int p = 0; p < SPLIT; p++)
            s += g_ssk[((size_t)bh * SPLIT + p) * HD + tid - 48];
        invk[tid - 48] = 1.f / fmaxf(sqrtf(s), 1e-12f);
    }

    const float* gin = g_gram + (size_t)bh * SPLIT * (HD * HD);
    float sums[3][3];
#pragma unroll
    for (int i = 0; i < 3; i++)
#pragma unroll
        for (int j = 0; j < 3; j++) {
            float s = 0.f;
            int idx = (3 * r + i) * HD + 3 * c + j;
#pragma unroll
            for (int p = 0; p < SPLIT; p++)
                s += gin[p * (HD * HD) + idx];
            sums[i][j] = s;
        }
    __syncthreads();

    const float temp = temperature[h];
#pragma unroll
    for (int i = 0; i < 3; i++)
#pragma unroll
        for (int j = 0; j < 3; j++)
            attn[3 * r + i][3 * c + j] =
                sums[i][j] * invq[3 * r + i] * invk[3 * c + j] * temp;
    __syncthreads();

    const int lane = tid & 31;
    const int w = tid >> 5;
    for (int d = w; d < 48; d += 8) {
        float x1 = attn[d][lane];
        float x2 = (lane < 16) ? attn[d][32 + lane] : -1e30f;
        float m = fmaxf(x1, x2);
#pragma unroll
        for (int o = 16; o > 0; o >>= 1)
            m = fmaxf(m, __shfl_xor_sync(0xffffffffu, m, o));
        float p1 = expf(x1 - m);
        float p2 = (lane < 16) ? expf(x2 - m) : 0.f;
        float s = p1 + p2;
#pragma unroll
        for (int o = 16; o > 0; o >>= 1)
            s += __shfl_xor_sync(0xffffffffu, s, o);
        float inv = 1.f / s;
        __half* arow = g_attnh + (size_t)bh * (HD * HD) + d * HD;
        arow[lane] = __float2half_rn(p1 * inv);
        if (lane < 16) arow[32 + lane] = __float2half_rn(p2 * inv);
    }
}

// ---------------------------------------------------------------------------
// AV via mma (unchanged; its wait->sync ordering was already correct).
// ---------------------------------------------------------------------------
#define VROWB  112
#define ATN_B  (48 * VROWB)
#define VSTG   (128 * VROWB)
#define SMEM_AV (ATN_B + 2 * VSTG)

__global__ __launch_bounds__(256) void av_kernel()
{
    extern __shared__ char sm[];
    const int tid  = threadIdx.x;
    const int wid  = tid >> 5;
    const int lane = tid & 31;
    const int bh = blockIdx.x;
    const int sp = blockIdx.y;
    const int b = bh >> 4;
    const int h = bh & 15;
    const uint32_t sbase = smem_u32(sm);
    const uint32_t vs0 = sbase + ATN_B;

    const size_t tokflat = (size_t)b * NTOK + sp * TOKSP;

    for (int idx = tid; idx < 288; idx += 256) {
        int row = idx / 6, seg = idx % 6;
        uint4 val = *(const uint4*)(g_attnh + (size_t)bh * (HD * HD) + row * HD + seg * 8);
        *(uint4*)(sm + row * VROWB + seg * 16) = val;
    }

    int lrow[3], lseg[3];
#pragma unroll
    for (int i = 0; i < 3; i++) {
        int cc = tid + i * 256;
        lrow[i] = cc / 6;
        lseg[i] = cc % 6;
    }
    auto load_stage = [&](int t0, int rows, int s) {
#pragma unroll
        for (int i = 0; i < 3; i++) {
            if (lrow[i] < rows) {
                const __half* src = g_v + (tokflat + t0 + lrow[i]) * CH + h * HD + lseg[i] * 8;
                CP16(vs0 + s * VSTG + lrow[i] * VROWB + lseg[i] * 16, src);
            }
        }
    };

    const int g  = lane >> 3;
    const int r8 = lane & 7;
    const uint32_t a_off = (uint32_t)(((g & 1) * 8 + r8) * VROWB + (g >> 1) * 16);
    const uint32_t b_off = (uint32_t)((((g >> 1) & 1) * 8 + r8) * VROWB + (g & 1) * 16);

    load_stage(0, 128, 0);
    CP_COMMIT();
    __syncthreads();

    uint32_t bf[3][6][2];
#pragma unroll
    for (int k16 = 0; k16 < 3; k16++) {
#pragma unroll
        for (int j = 0; j < 3; j++) {
            uint32_t t4[4];
            ldsm4(t4, sbase + b_off + j * 16 * VROWB + k16 * 32);
            bf[k16][j * 2 + 0][0] = t4[0]; bf[k16][j * 2 + 0][1] = t4[1];
            bf[k16][j * 2 + 1][0] = t4[2]; bf[k16][j * 2 + 1][1] = t4[3];
        }
    }

    const int NIT = (TOKSP + 127) / 128;
    for (int it = 0; it < NIT; it++) {
        const int rows_this = min(128, TOKSP - it * 128);
        if (it + 1 < NIT) {
            load_stage((it + 1) * 128, min(128, TOKSP - (it + 1) * 128), (it + 1) & 1);
            CP_COMMIT();
            CP_WAIT1();
        } else {
            CP_WAIT0();
        }
        __syncthreads();

        if (wid * 16 < rows_this) {
            const uint32_t st = vs0 + (it & 1) * VSTG + wid * 16 * VROWB;
            float acc[6][4];
#pragma unroll
            for (int j = 0; j < 6; j++)
#pragma unroll
                for (int q = 0; q < 4; q++) acc[j][q] = 0.f;
#pragma unroll
            for (int k16 = 0; k16 < 3; k16++) {
                uint32_t af[4];
                ldsm4(af, st + a_off + k16 * 32);
#pragma unroll
                for (int j = 0; j < 6; j++)
                    mma16816(acc[j], af, bf[k16][j]);
            }
            const size_t trow = tokflat + it * 128 + wid * 16 + (lane >> 2);
#pragma unroll
            for (int j = 0; j < 6; j++) {
                int d = j * 8 + (lane & 3) * 2;
                __half2 h0 = __floats2half2_rn(acc[j][0], acc[j][1]);
                __half2 h1 = __floats2half2_rn(acc[j][2], acc[j][3]);
                *(__half2*)(g_ah + trow * CH + h * HD + d) = h0;
                *(__half2*)(g_ah + (trow + 8) * CH + h * HD + d) = h1;
            }
        }
        __syncthreads();
    }
}

// ---------------------------------------------------------------------------
// Launch sequence
// ---------------------------------------------------------------------------
extern "C" void kernel_launch(void* const* d_in, const int* in_sizes, int n_in,
                              void* d_out, int out_size)
{
    const float* x           = (const float*)d_in[0];
    const float* qkv_w       = (const float*)d_in[1];
    const float* temperature = (const float*)d_in[2];
    const float* proj_w      = (const float*)d_in[3];
    const float* proj_b      = (const float*)d_in[4];
    float* out = (float*)d_out;

    __half *xh, *ah, *wq, *wp, *qT, *kT, *vv;
    cudaGetSymbolAddress((void**)&xh, g_xh);
    cudaGetSymbolAddress((void**)&ah, g_ah);
    cudaGetSymbolAddress((void**)&wq, g_wq);
    cudaGetSymbolAddress((void**)&wp, g_wp);
    cudaGetSymbolAddress((void**)&qT, g_qT);
    cudaGetSymbolAddress((void**)&kT, g_kT);
    cudaGetSymbolAddress((void**)&vv, g_v);

    cudaFuncSetAttribute(gemm_qkv, cudaFuncAttributeMaxDynamicSharedMemorySize, SMEM_GEMM);
    cudaFuncSetAttribute(gemm_mma, cudaFuncAttributeMaxDynamicSharedMemorySize, SMEM_GEMM);
    cudaFuncSetAttribute(gram_kernel, cudaFuncAttributeMaxDynamicSharedMemorySize, SMEM_GRAM);
    cudaFuncSetAttribute(av_kernel, cudaFuncAttributeMaxDynamicSharedMemorySize, SMEM_AV);

    int n4 = MROWS * KDIM / 4;
    conv_kernel<<<(n4 + 255) / 256, 256>>>((const float4*)x, (__half2*)xh, n4);

    tconv_kernel<<<dim3((3 * CH) / 32, KDIM / 32), dim3(32, 8)>>>(
        qkv_w, wq, KDIM, 3 * CH);
    tconv_kernel<<<dim3(CH / 32, KDIM / 32), dim3(32, 8)>>>(
        proj_w, wp, KDIM, CH);

    gemm_qkv<<<dim3((3 * CH) / 128, MROWS / 128), 128, SMEM_GEMM>>>(
        xh, wq, qT, kT, vv);

    gram_kernel<<<dim3(BH, SPLIT), 256, SMEM_GRAM>>>();
    softmax_kernel<<<BH, 256>>>(temperature);
    av_kernel<<<dim3(BH, SPLIT), 256, SMEM_AV>>>();

    gemm_mma<<<dim3(CH / 128, MROWS / 128), 128, SMEM_GEMM>>>(
        ah, wp, out, CH, proj_b);
}

// round 15
// speedup vs baseline: 1.1142x; 1.0065x over previous
#include <cuda_runtime.h>
#include <cuda_fp16.h>
#include <math.h>
#include <stdint.h>
#include <stddef.h>

#define BATCH 16
#define NTOK  3136
#define CH    768
#define NH    16
#define HD    48
#define KDIM  768
#define MROWS (BATCH*NTOK)   // 50176
#define BH    (BATCH*NH)     // 256
#define SPLIT 7
#define TOKSP (NTOK/SPLIT)   // 448

// ----------------------------- device scratch ------------------------------
__device__ __half g_xh  [(size_t)MROWS * KDIM];
__device__ __half g_qT  [(size_t)BH * HD * NTOK];   // [bh][d][n] fp16
__device__ __half g_kT  [(size_t)BH * HD * NTOK];
__device__ __half g_v   [(size_t)MROWS * CH];       // [token][h*48+d] fp16
__device__ __half g_ah  [(size_t)MROWS * CH];
__device__ __half g_wq  [(size_t)(3 * CH) * KDIM];
__device__ __half g_wp  [(size_t)CH * KDIM];
__device__ float  g_gram[(size_t)BH * SPLIT * HD * HD];
__device__ float  g_ssq [(size_t)BH * SPLIT * HD];
__device__ float  g_ssk [(size_t)BH * SPLIT * HD];
__device__ __half g_attnh[(size_t)BH * HD * HD];

// ----------------------------- PTX helpers ---------------------------------
__device__ __forceinline__ uint32_t smem_u32(const void* p) {
    return (uint32_t)__cvta_generic_to_shared(p);
}

__device__ __forceinline__ void mma16816(float* c, const uint32_t* a, const uint32_t* b) {
    asm volatile(
        "mma.sync.aligned.m16n8k16.row.col.f32.f16.f16.f32 "
        "{%0,%1,%2,%3}, {%4,%5,%6,%7}, {%8,%9}, {%0,%1,%2,%3};"
        : "+f"(c[0]), "+f"(c[1]), "+f"(c[2]), "+f"(c[3])
        : "r"(a[0]), "r"(a[1]), "r"(a[2]), "r"(a[3]), "r"(b[0]), "r"(b[1]));
}

__device__ __forceinline__ void ldsm4(uint32_t* r, uint32_t addr) {
    asm volatile("ldmatrix.sync.aligned.m8n8.x4.shared.b16 {%0,%1,%2,%3}, [%4];"
        : "=r"(r[0]), "=r"(r[1]), "=r"(r[2]), "=r"(r[3]) : "r"(addr));
}

#define CP16(dst, src) \
    asm volatile("cp.async.cg.shared.global [%0], [%1], 16;" :: "r"(dst), "l"(src))
#define CP_COMMIT()  asm volatile("cp.async.commit_group;" ::: "memory")
#define CP_WAIT0()   asm volatile("cp.async.wait_group 0;" ::: "memory")
#define CP_WAIT1()   asm volatile("cp.async.wait_group 1;" ::: "memory")

// ---------------------------------------------------------------------------
// fp32 -> fp16 convert: 2 x float4 in, 1 x 16B out per thread (MLP=2, STG.128)
// ---------------------------------------------------------------------------
__global__ void conv_kernel(const float4* __restrict__ in,
                            uint4* __restrict__ out, int n8)
{
    int i = blockIdx.x * blockDim.x + threadIdx.x;
    if (i >= n8) return;
    float4 a = in[2 * i + 0];
    float4 b = in[2 * i + 1];
    __half2 h[4];
    h[0] = __floats2half2_rn(a.x, a.y);
    h[1] = __floats2half2_rn(a.z, a.w);
    h[2] = __floats2half2_rn(b.x, b.y);
    h[3] = __floats2half2_rn(b.z, b.w);
    out[i] = *(uint4*)h;
}

// ---------------------------------------------------------------------------
// Transpose + convert: W[K,N] fp32 -> Wt [N,K] fp16
// ---------------------------------------------------------------------------
__global__ void tconv_kernel(const float* __restrict__ W,
                             __half* __restrict__ T, int K, int N)
{
    __shared__ float tile[32][33];
    int n0 = blockIdx.x * 32, k0 = blockIdx.y * 32;
    int tx = threadIdx.x, ty = threadIdx.y;   // 32 x 8
#pragma unroll
    for (int j = 0; j < 32; j += 8)
        tile[ty + j][tx] = W[(size_t)(k0 + ty + j) * N + n0 + tx];
    __syncthreads();
#pragma unroll
    for (int j = 0; j < 32; j += 8)
        T[(size_t)(n0 + ty + j) * K + k0 + tx] = __float2half_rn(tile[tx][ty + j]);
}

// ---------------------------------------------------------------------------
// GEMM geometry: CTA tile 128x128, 128 threads (4 warps @ 64x64), K-chunk 64,
// 2-stage pipeline, ONE barrier per iteration (wait -> sync -> load order).
// 3 CTAs/SM. Rows 144B (9x16B, conflict-free).
// ---------------------------------------------------------------------------
#define ROWB     144
#define A_B      (128 * ROWB)                // 18432
#define STAGE_B  (256 * ROWB)                // 36864
#define SMEM_GEMM (2 * STAGE_B)              // 73728
#define KC       64
#define NITER    (KDIM / KC)                 // 12

#define GEMM_PRELUDE(Aptr, Bptr)                                               \
    extern __shared__ char sm[];                                               \
    const int tid  = threadIdx.x;                                              \
    const int wid  = tid >> 5;                                                 \
    const int lane = tid & 31;                                                 \
    const size_t m0 = (size_t)blockIdx.y * 128;                                \
    const size_t n0 = (size_t)blockIdx.x * 128;                                \
    const int lr0  = tid >> 3;            /* 0..15 */                          \
    const int lseg = tid & 7;                                                  \
    const uint32_t sbase = smem_u32(sm);                                       \
    const uint32_t dA = sbase + lr0 * ROWB + lseg * 16;                        \
    const uint32_t dB = sbase + A_B + lr0 * ROWB + lseg * 16;                  \
    const __half* sA = (Aptr) + (m0 + lr0) * KDIM + lseg * 8;                  \
    const __half* sB = (Bptr) + (n0 + lr0) * KDIM + lseg * 8;                  \
    auto load_stage = [&](int kc, int s) {                                     \
        _Pragma("unroll")                                                      \
        for (int i = 0; i < 8; i++)                                            \
            CP16(dA + s * STAGE_B + i * 16 * ROWB, sA + kc + (size_t)i * 16 * KDIM); \
        _Pragma("unroll")                                                      \
        for (int i = 0; i < 8; i++)                                            \
            CP16(dB + s * STAGE_B + i * 16 * ROWB, sB + kc + (size_t)i * 16 * KDIM); \
    };                                                                         \
    const int warp_m = wid & 1;                                                \
    const int warp_n = wid >> 1;                                               \
    const int gq  = lane >> 3;                                                 \
    const int r8 = lane & 7;                                                   \
    const uint32_t a_off = (uint32_t)((warp_m * 64 + (gq & 1) * 8 + r8) * ROWB + (gq >> 1) * 16); \
    const uint32_t b_off = (uint32_t)((warp_n * 64 + ((gq >> 1) & 1) * 8 + r8) * ROWB + (gq & 1) * 16); \
    float acc[4][8][4];                                                        \
    _Pragma("unroll")                                                          \
    for (int i = 0; i < 4; i++)                                                \
        _Pragma("unroll")                                                      \
        for (int j = 0; j < 8; j++)                                            \
            _Pragma("unroll")                                                  \
            for (int q = 0; q < 4; q++) acc[i][j][q] = 0.f;                    \
    load_stage(0, 0);                                                          \
    CP_COMMIT();                                                               \
    for (int it = 0; it < NITER; it++) {                                       \
        const int s = it & 1;                                                  \
        CP_WAIT0();                   /* load(it) retired (issued last iter) */ \
        __syncthreads();              /* stage s visible CTA-wide; s^1 free */ \
        if (it + 1 < NITER) {                                                  \
            load_stage((it + 1) * KC, s ^ 1);                                  \
            CP_COMMIT();                                                       \
        }                                                                      \
        const uint32_t st = sbase + s * STAGE_B;                               \
        _Pragma("unroll")                                                      \
        for (int kk = 0; kk < 4; kk++) {                                       \
            const uint32_t kb = kk * 32;                                       \
            uint32_t af[4][4];                                                 \
            _Pragma("unroll")                                                  \
            for (int mt = 0; mt < 4; mt++)                                     \
                ldsm4(af[mt], st + a_off + mt * 16 * ROWB + kb);               \
            _Pragma("unroll")                                                  \
            for (int j2 = 0; j2 < 2; j2++) {                                   \
                uint32_t bf[4][2], t4[4];                                      \
                ldsm4(t4, st + A_B + b_off + (j2 * 2 + 0) * 16 * ROWB + kb);   \
                bf[0][0] = t4[0]; bf[0][1] = t4[1];                            \
                bf[1][0] = t4[2]; bf[1][1] = t4[3];                            \
                ldsm4(t4, st + A_B + b_off + (j2 * 2 + 1) * 16 * ROWB + kb);   \
                bf[2][0] = t4[0]; bf[2][1] = t4[1];                            \
                bf[3][0] = t4[2]; bf[3][1] = t4[3];                            \
                _Pragma("unroll")                                              \
                for (int mt = 0; mt < 4; mt++)                                 \
                    _Pragma("unroll")                                          \
                    for (int nt = 0; nt < 4; nt++)                             \
                        mma16816(acc[mt][j2 * 4 + nt], af[mt], bf[nt]);        \
            }                                                                  \
        }                                                                      \
    }

// ---------------------------------------------------------------------------
// GEMM1: qkv = x @ qkv_w^T, fp16 outputs in XCA layouts.
// ---------------------------------------------------------------------------
__global__ __launch_bounds__(128, 3) void gemm_qkv(
    const __half* __restrict__ A, const __half* __restrict__ B,
    __half* __restrict__ Qt, __half* __restrict__ Kt, __half* __restrict__ Vp)
{
    GEMM_PRELUDE(A, B)

    // ---- epilogue ----
    const int section = (int)(n0 / 768);   // 0:q 1:k 2:v
    const int crow = warp_m * 64 + (lane >> 2);
    const int ccol = warp_n * 64 + (lane & 3) * 2;

    if (section == 2) {
#pragma unroll
        for (int mt = 0; mt < 4; mt++) {
#pragma unroll
            for (int nt = 0; nt < 8; nt++) {
                size_t row = m0 + crow + mt * 16;
                int vc = (int)(n0 - 1536) + ccol + nt * 8;
                __half2 h0 = __floats2half2_rn(acc[mt][nt][0], acc[mt][nt][1]);
                __half2 h1 = __floats2half2_rn(acc[mt][nt][2], acc[mt][nt][3]);
                *(__half2*)(Vp + row * CH + vc) = h0;
                *(__half2*)(Vp + (row + 8) * CH + vc) = h1;
            }
        }
    } else {
        __syncthreads();   // all warps done reading final stage before reuse
        // transpose through smem: [col 128][token 128], row stride 272B
#pragma unroll
        for (int mt = 0; mt < 4; mt++) {
#pragma unroll
            for (int nt = 0; nt < 8; nt++) {
                int col = ccol + nt * 8;
                int row = crow + mt * 16;
                *(__half*)(sm + (size_t)col * 272 + row * 2)             = __float2half_rn(acc[mt][nt][0]);
                *(__half*)(sm + (size_t)(col + 1) * 272 + row * 2)       = __float2half_rn(acc[mt][nt][1]);
                *(__half*)(sm + (size_t)col * 272 + (row + 8) * 2)       = __float2half_rn(acc[mt][nt][2]);
                *(__half*)(sm + (size_t)(col + 1) * 272 + (row + 8) * 2) = __float2half_rn(acc[mt][nt][3]);
            }
        }
        __syncthreads();
        __half* dst = (section == 0) ? Qt : Kt;
        const int base_gc = (int)n0 - section * 768;
#pragma unroll
        for (int i = 0; i < 16; i++) {
            int idx = tid + i * 128;          // 0..2047
            int col = idx >> 4, tv = idx & 15;
            uint4 val = *(uint4*)(sm + (size_t)col * 272 + tv * 16);
            int gc = base_gc + col;
            int hh = gc / 48, dd = gc - hh * 48;
            size_t tok = m0 + tv * 8;
            int b = (int)(tok / NTOK);
            int n = (int)(tok - (size_t)b * NTOK);
            *(uint4*)(dst + ((size_t)(b * 16 + hh) * HD + dd) * NTOK + n) = val;
        }
    }
}

// ---------------------------------------------------------------------------
// GEMM2: out = att @ proj_w^T + bias, fp32 out.
// ---------------------------------------------------------------------------
__global__ __launch_bounds__(128, 3) void gemm_mma(
    const __half* __restrict__ A, const __half* __restrict__ B,
    float* __restrict__ C, int N, const float* __restrict__ bias)
{
    GEMM_PRELUDE(A, B)

    const int crow = warp_m * 64 + (lane >> 2);
    const int ccol = warp_n * 64 + (lane & 3) * 2;
#pragma unroll
    for (int mt = 0; mt < 4; mt++) {
#pragma unroll
        for (int nt = 0; nt < 8; nt++) {
            float b0 = __ldg(bias + n0 + ccol + nt * 8);
            float b1 = __ldg(bias + n0 + ccol + nt * 8 + 1);
            float2 v0 = {acc[mt][nt][0] + b0, acc[mt][nt][1] + b1};
            float2 v1 = {acc[mt][nt][2] + b0, acc[mt][nt][3] + b1};
            float* p0 = C + (m0 + crow + mt * 16) * (size_t)N + n0 + ccol + nt * 8;
            float* p1 = p0 + 8 * (size_t)N;
            *(float2*)p0 = v0;
            *(float2*)p1 = v1;
        }
    }
}

// ---------------------------------------------------------------------------
// Gram via mma: one barrier per chunk (wait -> sync -> load order).
// ---------------------------------------------------------------------------
#define GROWB  144
#define GTILE  (48 * GROWB)
#define GSTAGE (2 * GTILE)
#define GRED   (2 * GSTAGE)
#define SMEM_GRAM (GRED + 4 * HD * HD * 4)

__global__ __launch_bounds__(256) void gram_kernel()
{
    extern __shared__ char sm[];
    const int tid  = threadIdx.x;
    const int wid  = tid >> 5;
    const int lane = tid & 31;
    const int bh = blockIdx.x;
    const int sp = blockIdx.y;
    const uint32_t sbase = smem_u32(sm);

    const __half* qbase = g_qT + (size_t)bh * HD * NTOK + sp * TOKSP;
    const __half* kbase = g_kT + (size_t)bh * HD * NTOK + sp * TOKSP;

    uint32_t ldst[3];
    const __half* lsrc[3];
#pragma unroll
    for (int i = 0; i < 3; i++) {
        int c = tid + i * 256;
        int cc = (c < 384) ? c : c - 384;
        int r = cc >> 3, seg = cc & 7;
        ldst[i] = sbase + ((c < 384) ? 0 : GTILE) + r * GROWB + seg * 16;
        lsrc[i] = ((c < 384) ? qbase : kbase) + (size_t)r * NTOK + seg * 8;
    }
    auto load_stage = [&](int kc, int s) {
#pragma unroll
        for (int i = 0; i < 3; i++)
            CP16(ldst[i] + s * GSTAGE, lsrc[i] + kc);
    };

    const int g  = lane >> 3;
    const int r8 = lane & 7;
    const uint32_t a_off = (uint32_t)(((g & 1) * 8 + r8) * GROWB + (g >> 1) * 16);
    const uint32_t b_off = (uint32_t)((((g >> 1) & 1) * 8 + r8) * GROWB + (g & 1) * 16);

    float acc[3][6][4];
#pragma unroll
    for (int i = 0; i < 3; i++)
#pragma unroll
        for (int j = 0; j < 6; j++)
#pragma unroll
            for (int q = 0; q < 4; q++) acc[i][j][q] = 0.f;

    const int t2 = ((wid - 4) & 1) * 32 + lane;
    const bool isq = (wid == 4 || wid == 5);
    float nsum = 0.f;

    load_stage(0, 0);
    CP_COMMIT();

    for (int c = 0; c < SPLIT; c++) {
        CP_WAIT0();                    // stage c retired (mine)
        __syncthreads();               // visible CTA-wide; stage c^1 free
        if (c + 1 < SPLIT) {
            load_stage((c + 1) * 64, (c + 1) & 1);
            CP_COMMIT();
        }
        const uint32_t st = sbase + (c & 1) * GSTAGE;
        if (wid < 4) {
            const uint32_t kb = wid * 32;
            uint32_t af[3][4], bf[6][2];
#pragma unroll
            for (int mt = 0; mt < 3; mt++)
                ldsm4(af[mt], st + a_off + mt * 16 * GROWB + kb);
#pragma unroll
            for (int j = 0; j < 3; j++) {
                uint32_t t4[4];
                ldsm4(t4, st + GTILE + b_off + j * 16 * GROWB + kb);
                bf[j * 2 + 0][0] = t4[0]; bf[j * 2 + 0][1] = t4[1];
                bf[j * 2 + 1][0] = t4[2]; bf[j * 2 + 1][1] = t4[3];
            }
#pragma unroll
            for (int mt = 0; mt < 3; mt++)
#pragma unroll
                for (int nt = 0; nt < 6; nt++)
                    mma16816(acc[mt][nt], af[mt], bf[nt]);
        } else if (t2 < 48) {
            const uint32_t rowaddr = st + (isq ? 0 : GTILE) + t2 * GROWB;
#pragma unroll
            for (int i = 0; i < 32; i++) {
                uint32_t u;
                asm volatile("ld.shared.b32 %0, [%1];" : "=r"(u) : "r"(rowaddr + i * 4));
                float2 f = __half22float2(*(__half2*)&u);
                nsum = fmaf(f.x, f.x, nsum);
                nsum = fmaf(f.y, f.y, nsum);
            }
        }
    }

    if (wid >= 4 && t2 < 48) {
        float* dst = isq ? g_ssq : g_ssk;
        dst[((size_t)bh * SPLIT + sp) * HD + t2] = nsum;
    }

    __syncthreads();
    float* red = (float*)(sm + GRED);
    if (wid < 4) {
        float* rw = red + wid * (HD * HD);
#pragma unroll
        for (int mt = 0; mt < 3; mt++)
#pragma unroll
            for (int nt = 0; nt < 6; nt++) {
                int row = mt * 16 + (lane >> 2);
                int col = nt * 8 + (lane & 3) * 2;
                *(float2*)(rw + row * HD + col) = *(float2*)&acc[mt][nt][0];
                *(float2*)(rw + (row + 8) * HD + col) = *(float2*)&acc[mt][nt][2];
            }
    }
    __syncthreads();
    float* gout = g_gram + ((size_t)bh * SPLIT + sp) * (HD * HD);
#pragma unroll
    for (int i = 0; i < 9; i++) {
        int el = tid + i * 256;
        gout[el] = red[el] + red[HD * HD + el] + red[2 * HD * HD + el] + red[3 * HD * HD + el];
    }
}

// ---------------------------------------------------------------------------
// Softmax (unchanged).
// ---------------------------------------------------------------------------
__global__ __launch_bounds__(256) void softmax_kernel(const float* __restrict__ temperature)
{
    __shared__ float attn[48][52];
    __shared__ float invq[48];
    __shared__ float invk[48];

    const int bh = blockIdx.x;
    const int h = bh & 15;
    const int tid = threadIdx.x;
    const int r = tid >> 4;
    const int c = tid & 15;

    if (tid < 48) {
        float s = 0.f;
#pragma unroll
        for (int p = 0; p < SPLIT; p++)
            s += g_ssq[((size_t)bh * SPLIT + p) * HD + tid];
        invq[tid] = 1.f / fmaxf(sqrtf(s), 1e-12f);
    } else if (tid < 96) {
        float s = 0.f;
#pragma unroll
        for (int p = 0; p < SPLIT; p++)
            s += g_ssk[((size_t)bh * SPLIT + p) * HD + tid - 48];
        invk[tid - 48] = 1.f / fmaxf(sqrtf(s), 1e-12f);
    }

    const float* gin = g_gram + (size_t)bh * SPLIT * (HD * HD);
    float sums[3][3];
#pragma unroll
    for (int i = 0; i < 3; i++)
#pragma unroll
        for (int j = 0; j < 3; j++) {
            float s = 0.f;
            int idx = (3 * r + i) * HD + 3 * c + j;
#pragma unroll
            for (int p = 0; p < SPLIT; p++)
                s += gin[p * (HD * HD) + idx];
            sums[i][j] = s;
        }
    __syncthreads();

    const float temp = temperature[h];
#pragma unroll
    for (int i = 0; i < 3; i++)
#pragma unroll
        for (int j = 0; j < 3; j++)
            attn[3 * r + i][3 * c + j] =
                sums[i][j] * invq[3 * r + i] * invk[3 * c + j] * temp;
    __syncthreads();

    const int lane = tid & 31;
    const int w = tid >> 5;
    for (int d = w; d < 48; d += 8) {
        float x1 = attn[d][lane];
        float x2 = (lane < 16) ? attn[d][32 + lane] : -1e30f;
        float m = fmaxf(x1, x2);
#pragma unroll
        for (int o = 16; o > 0; o >>= 1)
            m = fmaxf(m, __shfl_xor_sync(0xffffffffu, m, o));
        float p1 = expf(x1 - m);
        float p2 = (lane < 16) ? expf(x2 - m) : 0.f;
        float s = p1 + p2;
#pragma unroll
        for (int o = 16; o > 0; o >>= 1)
            s += __shfl_xor_sync(0xffffffffu, s, o);
        float inv = 1.f / s;
        __half* arow = g_attnh + (size_t)bh * (HD * HD) + d * HD;
        arow[lane] = __float2half_rn(p1 * inv);
        if (lane < 16) arow[32 + lane] = __float2half_rn(p2 * inv);
    }
}

// ---------------------------------------------------------------------------
// AV via mma (unchanged).
// ---------------------------------------------------------------------------
#define VROWB  112
#define ATN_B  (48 * VROWB)
#define VSTG   (128 * VROWB)
#define SMEM_AV (ATN_B + 2 * VSTG)

__global__ __launch_bounds__(256) void av_kernel()
{
    extern __shared__ char sm[];
    const int tid  = threadIdx.x;
    const int wid  = tid >> 5;
    const int lane = tid & 31;
    const int bh = blockIdx.x;
    const int sp = blockIdx.y;
    const int b = bh >> 4;
    const int h = bh & 15;
    const uint32_t sbase = smem_u32(sm);
    const uint32_t vs0 = sbase + ATN_B;

    const size_t tokflat = (size_t)b * NTOK + sp * TOKSP;

    for (int idx = tid; idx < 288; idx += 256) {
        int row = idx / 6, seg = idx % 6;
        uint4 val = *(const uint4*)(g_attnh + (size_t)bh * (HD * HD) + row * HD + seg * 8);
        *(uint4*)(sm + row * VROWB + seg * 16) = val;
    }

    int lrow[3], lseg[3];
#pragma unroll
    for (int i = 0; i < 3; i++) {
        int cc = tid + i * 256;
        lrow[i] = cc / 6;
        lseg[i] = cc % 6;
    }
    auto load_stage = [&](int t0, int rows, int s) {
#pragma unroll
        for (int i = 0; i < 3; i++) {
            if (lrow[i] < rows) {
                const __half* src = g_v + (tokflat + t0 + lrow[i]) * CH + h * HD + lseg[i] * 8;
                CP16(vs0 + s * VSTG + lrow[i] * VROWB + lseg[i] * 16, src);
            }
        }
    };

    const int g  = lane >> 3;
    const int r8 = lane & 7;
    const uint32_t a_off = (uint32_t)(((g & 1) * 8 + r8) * VROWB + (g >> 1) * 16);
    const uint32_t b_off = (uint32_t)((((g >> 1) & 1) * 8 + r8) * VROWB + (g & 1) * 16);

    load_stage(0, 128, 0);
    CP_COMMIT();
    __syncthreads();

    uint32_t bf[3][6][2];
#pragma unroll
    for (int k16 = 0; k16 < 3; k16++) {
#pragma unroll
        for (int j = 0; j < 3; j++) {
            uint32_t t4[4];
            ldsm4(t4, sbase + b_off + j * 16 * VROWB + k16 * 32);
            bf[k16][j * 2 + 0][0] = t4[0]; bf[k16][j * 2 + 0][1] = t4[1];
            bf[k16][j * 2 + 1][0] = t4[2]; bf[k16][j * 2 + 1][1] = t4[3];
        }
    }

    const int NIT = (TOKSP + 127) / 128;
    for (int it = 0; it < NIT; it++) {
        const int rows_this = min(128, TOKSP - it * 128);
        if (it + 1 < NIT) {
            load_stage((it + 1) * 128, min(128, TOKSP - (it + 1) * 128), (it + 1) & 1);
            CP_COMMIT();
            CP_WAIT1();
        } else {
            CP_WAIT0();
        }
        __syncthreads();

        if (wid * 16 < rows_this) {
            const uint32_t st = vs0 + (it & 1) * VSTG + wid * 16 * VROWB;
            float acc[6][4];
#pragma unroll
            for (int j = 0; j < 6; j++)
#pragma unroll
                for (int q = 0; q < 4; q++) acc[j][q] = 0.f;
#pragma unroll
            for (int k16 = 0; k16 < 3; k16++) {
                uint32_t af[4];
                ldsm4(af, st + a_off + k16 * 32);
#pragma unroll
                for (int j = 0; j < 6; j++)
                    mma16816(acc[j], af, bf[k16][j]);
            }
            const size_t trow = tokflat + it * 128 + wid * 16 + (lane >> 2);
#pragma unroll
            for (int j = 0; j < 6; j++) {
                int d = j * 8 + (lane & 3) * 2;
                __half2 h0 = __floats2half2_rn(acc[j][0], acc[j][1]);
                __half2 h1 = __floats2half2_rn(acc[j][2], acc[j][3]);
                *(__half2*)(g_ah + trow * CH + h * HD + d) = h0;
                *(__half2*)(g_ah + (trow + 8) * CH + h * HD + d) = h1;
            }
        }
        __syncthreads();
    }
}

// ---------------------------------------------------------------------------
// Launch sequence
// ---------------------------------------------------------------------------
extern "C" void kernel_launch(void* const* d_in, const int* in_sizes, int n_in,
                              void* d_out, int out_size)
{
    const float* x           = (const float*)d_in[0];
    const float* qkv_w       = (const float*)d_in[1];
    const float* temperature = (const float*)d_in[2];
    const float* proj_w      = (const float*)d_in[3];
    const float* proj_b      = (const float*)d_in[4];
    float* out = (float*)d_out;

    __half *xh, *ah, *wq, *wp, *qT, *kT, *vv;
    cudaGetSymbolAddress((void**)&xh, g_xh);
    cudaGetSymbolAddress((void**)&ah, g_ah);
    cudaGetSymbolAddress((void**)&wq, g_wq);
    cudaGetSymbolAddress((void**)&wp, g_wp);
    cudaGetSymbolAddress((void**)&qT, g_qT);
    cudaGetSymbolAddress((void**)&kT, g_kT);
    cudaGetSymbolAddress((void**)&vv, g_v);

    cudaFuncSetAttribute(gemm_qkv, cudaFuncAttributeMaxDynamicSharedMemorySize, SMEM_GEMM);
    cudaFuncSetAttribute(gemm_mma, cudaFuncAttributeMaxDynamicSharedMemorySize, SMEM_GEMM);
    cudaFuncSetAttribute(gram_kernel, cudaFuncAttributeMaxDynamicSharedMemorySize, SMEM_GRAM);
    cudaFuncSetAttribute(av_kernel, cudaFuncAttributeMaxDynamicSharedMemorySize, SMEM_AV);

    int n8 = MROWS * KDIM / 8;
    conv_kernel<<<(n8 + 255) / 256, 256>>>((const float4*)x, (uint4*)xh, n8);

    tconv_kernel<<<dim3((3 * CH) / 32, KDIM / 32), dim3(32, 8)>>>(
        qkv_w, wq, KDIM, 3 * CH);
    tconv_kernel<<<dim3(CH / 32, KDIM / 32), dim3(32, 8)>>>(
        proj_w, wp, KDIM, CH);

    gemm_qkv<<<dim3((3 * CH) / 128, MROWS / 128), 128, SMEM_GEMM>>>(
        xh, wq, qT, kT, vv);

    gram_kernel<<<dim3(BH, SPLIT), 256, SMEM_GRAM>>>();
    softmax_kernel<<<BH, 256>>>(temperature);
    av_kernel<<<dim3(BH, SPLIT), 256, SMEM_AV>>>();

    gemm_mma<<<dim3(CH / 128, MROWS / 128), 128, SMEM_GEMM>>>(
        ah, wp, out, CH, proj_b);
}